// round 3
// baseline (speedup 1.0000x reference)
#include <cuda_runtime.h>
#include <cuda_bf16.h>
#include <cstdint>
#include <math.h>

// Problem constants
#define SEQ 1536
#define BATCH 2
#define DMODEL 768
#define NHEAD 24
#define DHEAD 32
#define FFDIM 3072
#define NTOK (SEQ * BATCH)          // 3072 tokens, token t = s*B + b
#define QKVDIM (3 * DMODEL)         // 2304
#define ATTN_SCALE 0.17677669529663688f  // 1/sqrt(32)

// ---------------- scratch (device globals; no allocs allowed) ----------------
__device__ float g_x[NTOK * DMODEL];      // residual stream (S,B,D)
__device__ float g_h[NTOK * DMODEL];      // LN output
__device__ float g_qkv[NTOK * QKVDIM];    // qkv projection
__device__ float g_ctx[NTOK * DMODEL];    // attention context
__device__ float g_m[NTOK * FFDIM];       // gelu(fc) output

// ---------------- embedding ----------------
__global__ void embed_kernel(const int* __restrict__ ids, const int* __restrict__ pos,
                             const float* __restrict__ wte, const float* __restrict__ wpe,
                             float* __restrict__ x) {
    int t = blockIdx.x;               // t = s*B + b
    int s = t / BATCH, b = t % BATCH;
    int id = ids[b * SEQ + s];
    int p  = pos[b * SEQ + s];
    const float* te = wte + (size_t)id * DMODEL;
    const float* pe = wpe + (size_t)p * DMODEL;
    for (int d = threadIdx.x; d < DMODEL; d += blockDim.x)
        x[(size_t)t * DMODEL + d] = te[d] + pe[d];
}

// ---------------- layernorm (row of 768, one block per token) ----------------
__global__ void ln_kernel(const float* __restrict__ in, const float* __restrict__ w,
                          const float* __restrict__ b, float* __restrict__ out) {
    int t = blockIdx.x;
    const float* row = in + (size_t)t * DMODEL;
    float s = 0.f, ss = 0.f;
    for (int d = threadIdx.x; d < DMODEL; d += 256) {
        float v = row[d];
        s += v;
        ss = fmaf(v, v, ss);
    }
    __shared__ float red0[8], red1[8];
    __shared__ float s_mu, s_inv;
    int lane = threadIdx.x & 31, wid = threadIdx.x >> 5;
#pragma unroll
    for (int o = 16; o; o >>= 1) {
        s  += __shfl_xor_sync(0xffffffffu, s, o);
        ss += __shfl_xor_sync(0xffffffffu, ss, o);
    }
    if (lane == 0) { red0[wid] = s; red1[wid] = ss; }
    __syncthreads();
    if (threadIdx.x == 0) {
        float a = 0.f, c = 0.f;
#pragma unroll
        for (int i = 0; i < 8; i++) { a += red0[i]; c += red1[i]; }
        float mu = a * (1.0f / DMODEL);
        float var = c * (1.0f / DMODEL) - mu * mu;
        s_mu = mu;
        s_inv = rsqrtf(var + 1e-5f);
    }
    __syncthreads();
    float mu = s_mu, inv = s_inv;
    for (int d = threadIdx.x; d < DMODEL; d += 256)
        out[(size_t)t * DMODEL + d] = (row[d] - mu) * inv * w[d] + b[d];
}

// ---------------- TF32 tensor-core GEMM ----------------
// C[m][n] = sum_k A[m][k] * W[n][k]  (+bias, +epilogue)
// A: (M,K) row-major fp32, W: (N,K) row-major fp32.
// Tile: BM=128, BN=128, BK=32. 256 threads = 8 warps (4 along M x 2 along N).
// Warp tile 32x64 = 2 x 8 mma.m16n8k8 tiles. fp32 accumulate.
// SMEM layout word_off(k,m) = (k>>2)*512 + m*4 + (k&3):
//   - global->shared: float4 along K maps to 4 contiguous words (STS.128, conflict-free)
//   - fragment LDS.32: bank = (m%8)*4 + (k%4), bijective over warp lanes -> conflict-free
// EPI: 0 = bias; 1 = bias + residual; 2 = bias + exact GELU

__device__ __forceinline__ uint32_t f2tf32(float f) {
    uint32_t u;
    asm("cvt.rna.tf32.f32 %0, %1;" : "=r"(u) : "f"(f));
    return u;
}

__device__ __forceinline__ void mma_tf32(float* d, const uint32_t* a, const uint32_t* b) {
    asm volatile(
        "mma.sync.aligned.m16n8k8.row.col.f32.tf32.tf32.f32 "
        "{%0,%1,%2,%3}, {%4,%5,%6,%7}, {%8,%9}, {%0,%1,%2,%3};"
        : "+f"(d[0]), "+f"(d[1]), "+f"(d[2]), "+f"(d[3])
        : "r"(a[0]), "r"(a[1]), "r"(a[2]), "r"(a[3]), "r"(b[0]), "r"(b[1]));
}

template <int EPI>
__global__ void __launch_bounds__(256) gemm_tc(const float* __restrict__ A,
                                               const float* __restrict__ W,
                                               const float* __restrict__ bias,
                                               const float* __restrict__ res,
                                               float* __restrict__ C,
                                               int M, int N, int K) {
    __shared__ uint32_t As[32 * 128];   // 16 KB
    __shared__ uint32_t Bs[32 * 128];   // 16 KB

    int tid = threadIdx.x;
    int m0 = blockIdx.y * 128, n0 = blockIdx.x * 128;
    int warp = tid >> 5, lane = tid & 31;
    int wm = warp & 3, wn = warp >> 2;        // 4 warps M, 2 warps N
    int gid = lane >> 2, tig = lane & 3;

    float acc[2][8][4];
#pragma unroll
    for (int i = 0; i < 2; i++)
#pragma unroll
        for (int j = 0; j < 8; j++)
#pragma unroll
            for (int r = 0; r < 4; r++) acc[i][j][r] = 0.f;

    // global load mapping: 256 threads, each loads 4 float4 from A and 4 from W per BK step
    int lrow = tid >> 3;          // 0..31
    int lk4  = tid & 7;           // float4 index along K (k = lk4*4)
    const float* Ag = A + (size_t)(m0 + lrow) * K + lk4 * 4;
    const float* Wg = W + (size_t)(n0 + lrow) * K + lk4 * 4;
    int sbase = lk4 * 512 + lrow * 4;   // word offset for (k=lk4*4, m=lrow)

    float4 pa[4], pb[4];
#pragma unroll
    for (int p = 0; p < 4; p++) {
        pa[p] = *(const float4*)(Ag + (size_t)(p * 32) * K);
        pb[p] = *(const float4*)(Wg + (size_t)(p * 32) * K);
    }

    for (int k0 = 0; k0 < K; k0 += 32) {
        __syncthreads();   // previous compute done before overwrite
#pragma unroll
        for (int p = 0; p < 4; p++) {
            uint4 ua = make_uint4(f2tf32(pa[p].x), f2tf32(pa[p].y), f2tf32(pa[p].z), f2tf32(pa[p].w));
            uint4 ub = make_uint4(f2tf32(pb[p].x), f2tf32(pb[p].y), f2tf32(pb[p].z), f2tf32(pb[p].w));
            *(uint4*)&As[sbase + p * 128] = ua;   // m advances by 32 -> +128 words
            *(uint4*)&Bs[sbase + p * 128] = ub;
        }
        __syncthreads();

        if (k0 + 32 < K) {
            const float* an = Ag + k0 + 32;
            const float* wn_ = Wg + k0 + 32;
#pragma unroll
            for (int p = 0; p < 4; p++) {
                pa[p] = *(const float4*)(an + (size_t)(p * 32) * K);
                pb[p] = *(const float4*)(wn_ + (size_t)(p * 32) * K);
            }
        }

#pragma unroll
        for (int c = 0; c < 4; c++) {           // k-chunk of 8
            int base = c * 1024;                // (c*2)*512
            uint32_t a[2][4], b[8][2];
#pragma unroll
            for (int i = 0; i < 2; i++) {
                int m = wm * 32 + i * 16 + gid;
                int o = base + m * 4 + tig;
                a[i][0] = As[o];        // (m,     k+tig)
                a[i][1] = As[o + 32];   // (m+8,   k+tig)
                a[i][2] = As[o + 512];  // (m,     k+tig+4)
                a[i][3] = As[o + 544];  // (m+8,   k+tig+4)
            }
#pragma unroll
            for (int j = 0; j < 8; j++) {
                int n = wn * 64 + j * 8 + gid;
                int o = base + n * 4 + tig;
                b[j][0] = Bs[o];        // (k+tig,   n)
                b[j][1] = Bs[o + 512];  // (k+tig+4, n)
            }
#pragma unroll
            for (int i = 0; i < 2; i++)
#pragma unroll
                for (int j = 0; j < 8; j++)
                    mma_tf32(acc[i][j], a[i], b[j]);
        }
    }

    // epilogue
#pragma unroll
    for (int i = 0; i < 2; i++) {
        int mrow = m0 + wm * 32 + i * 16 + gid;
#pragma unroll
        for (int j = 0; j < 8; j++) {
            int n = n0 + wn * 64 + j * 8 + tig * 2;
            float bn0 = bias[n], bn1 = bias[n + 1];
#pragma unroll
            for (int h = 0; h < 2; h++) {       // h=0: row mrow, h=1: row mrow+8
                int m = mrow + h * 8;
                float v0 = acc[i][j][h * 2 + 0] + bn0;
                float v1 = acc[i][j][h * 2 + 1] + bn1;
                if (EPI == 1) {
                    v0 += res[(size_t)m * N + n];
                    v1 += res[(size_t)m * N + n + 1];
                }
                if (EPI == 2) {
                    v0 = 0.5f * v0 * (1.0f + erff(v0 * 0.70710678118654752f));
                    v1 = 0.5f * v1 * (1.0f + erff(v1 * 0.70710678118654752f));
                }
                *(float2*)&C[(size_t)m * N + n] = make_float2(v0, v1);
            }
        }
    }
}

// ---------------- attention: warp-per-query-row online softmax ----------------
__global__ void attn_kernel(const float* __restrict__ qkv, float* __restrict__ ctx) {
    int warp = threadIdx.x >> 5, lane = threadIdx.x & 31;
    int sq = blockIdx.x * 8 + warp;        // query position
    int bh = blockIdx.y;
    int b = bh / NHEAD, h = bh % NHEAD;

    const float* qrow = qkv + ((size_t)sq * BATCH + b) * QKVDIM + h * 96;
    float q = qrow[lane] * ATTN_SCALE;

    float mmax = -1e30f, ssum = 0.f, acc = 0.f;
    for (int kk = 0; kk <= sq; kk++) {
        const float* kvrow = qkv + ((size_t)kk * BATCH + b) * QKVDIM + h * 96;
        float score = q * kvrow[32 + lane];
#pragma unroll
        for (int o = 16; o; o >>= 1) score += __shfl_xor_sync(0xffffffffu, score, o);
        float mnew = fmaxf(mmax, score);
        float corr = __expf(mmax - mnew);
        float p = __expf(score - mnew);
        ssum = ssum * corr + p;
        acc = acc * corr + p * kvrow[64 + lane];
        mmax = mnew;
    }
    ctx[((size_t)sq * BATCH + b) * DMODEL + h * DHEAD + lane] = acc / ssum;
}

// ---------------- launch ----------------
struct LayerW {
    const float *ln1w, *ln1b, *wqkv, *bqkv, *wo, *bo, *ln2w, *ln2b, *wfc, *bfc, *wproj, *bproj;
};

extern "C" void kernel_launch(void* const* d_in, const int* in_sizes, int n_in,
                              void* d_out, int out_size) {
    const int*   ids  = (const int*)d_in[0];
    const int*   pos  = (const int*)d_in[1];
    // d_in[2] = attn_mask (causal, known statically) — unused
    const float* wte  = (const float*)d_in[3];
    const float* wpe  = (const float*)d_in[4];
    LayerW L[2];
    for (int l = 0; l < 2; l++) {
        int o = 5 + l * 12;
        L[l].ln1w  = (const float*)d_in[o + 0];
        L[l].ln1b  = (const float*)d_in[o + 1];
        L[l].wqkv  = (const float*)d_in[o + 2];
        L[l].bqkv  = (const float*)d_in[o + 3];
        L[l].wo    = (const float*)d_in[o + 4];
        L[l].bo    = (const float*)d_in[o + 5];
        L[l].ln2w  = (const float*)d_in[o + 6];
        L[l].ln2b  = (const float*)d_in[o + 7];
        L[l].wfc   = (const float*)d_in[o + 8];
        L[l].bfc   = (const float*)d_in[o + 9];
        L[l].wproj = (const float*)d_in[o + 10];
        L[l].bproj = (const float*)d_in[o + 11];
    }
    const float* lnfw = (const float*)d_in[29];
    const float* lnfb = (const float*)d_in[30];
    float* out = (float*)d_out;

    float* x   = nullptr;  cudaGetSymbolAddress((void**)&x,   g_x);
    float* h   = nullptr;  cudaGetSymbolAddress((void**)&h,   g_h);
    float* qkv = nullptr;  cudaGetSymbolAddress((void**)&qkv, g_qkv);
    float* ctx = nullptr;  cudaGetSymbolAddress((void**)&ctx, g_ctx);
    float* mbuf= nullptr;  cudaGetSymbolAddress((void**)&mbuf,g_m);

    embed_kernel<<<NTOK, 256>>>(ids, pos, wte, wpe, x);

    for (int l = 0; l < 2; l++) {
        // LN1
        ln_kernel<<<NTOK, 256>>>(x, L[l].ln1w, L[l].ln1b, h);
        // qkv = h @ wqkv^T + bqkv : (3072, 2304)
        {
            dim3 g(QKVDIM / 128, NTOK / 128);
            gemm_tc<0><<<g, 256>>>(h, L[l].wqkv, L[l].bqkv, nullptr, qkv, NTOK, QKVDIM, DMODEL);
        }
        // attention -> ctx (3072, 768)
        {
            dim3 g(SEQ / 8, BATCH * NHEAD);
            attn_kernel<<<g, 256>>>(qkv, ctx);
        }
        // x = x + ctx @ wo^T + bo
        {
            dim3 g(DMODEL / 128, NTOK / 128);
            gemm_tc<1><<<g, 256>>>(ctx, L[l].wo, L[l].bo, x, x, NTOK, DMODEL, DMODEL);
        }
        // LN2
        ln_kernel<<<NTOK, 256>>>(x, L[l].ln2w, L[l].ln2b, h);
        // m = gelu(h @ wfc^T + bfc) : (3072, 3072)
        {
            dim3 g(FFDIM / 128, NTOK / 128);
            gemm_tc<2><<<g, 256>>>(h, L[l].wfc, L[l].bfc, nullptr, mbuf, NTOK, FFDIM, DMODEL);
        }
        // x = x + m @ wproj^T + bproj
        {
            dim3 g(DMODEL / 128, NTOK / 128);
            gemm_tc<1><<<g, 256>>>(mbuf, L[l].wproj, L[l].bproj, x, x, NTOK, DMODEL, FFDIM);
        }
    }

    // final LN straight into d_out
    ln_kernel<<<NTOK, 256>>>(x, lnfw, lnfb, out);
    (void)in_sizes; (void)n_in; (void)out_size;
}

// round 8
// speedup vs baseline: 3.2121x; 3.2121x over previous
#include <cuda_runtime.h>
#include <cuda_fp16.h>
#include <cstdint>
#include <math.h>

// Problem constants
#define SEQ 1536
#define BATCH 2
#define DMODEL 768
#define NHEAD 24
#define DHEAD 32
#define FFDIM 3072
#define NTOK (SEQ * BATCH)
#define QKVDIM (3 * DMODEL)
#define ATTN_SCALE 0.17677669529663688f

// ---------------- scratch ----------------
__device__ float g_x[NTOK * DMODEL];
__device__ float g_h[NTOK * DMODEL];
__device__ float g_qkv[NTOK * QKVDIM];
__device__ float g_ctx[NTOK * DMODEL];
__device__ float g_m[NTOK * FFDIM];

// ---------------- embedding ----------------
__global__ void embed_kernel(const int* __restrict__ ids, const int* __restrict__ pos,
                             const float* __restrict__ wte, const float* __restrict__ wpe,
                             float* __restrict__ x) {
    int t = blockIdx.x;
    int s = t / BATCH, b = t % BATCH;
    int id = ids[b * SEQ + s];
    int p  = pos[b * SEQ + s];
    const float* te = wte + (size_t)id * DMODEL;
    const float* pe = wpe + (size_t)p * DMODEL;
    for (int d = threadIdx.x; d < DMODEL; d += blockDim.x)
        x[(size_t)t * DMODEL + d] = te[d] + pe[d];
}

// ---------------- layernorm ----------------
__global__ void ln_kernel(const float* __restrict__ in, const float* __restrict__ w,
                          const float* __restrict__ b, float* __restrict__ out) {
    int t = blockIdx.x;
    const float* row = in + (size_t)t * DMODEL;
    float s = 0.f, ss = 0.f;
    for (int d = threadIdx.x; d < DMODEL; d += 256) {
        float v = row[d];
        s += v;
        ss = fmaf(v, v, ss);
    }
    __shared__ float red0[8], red1[8];
    __shared__ float s_mu, s_inv;
    int lane = threadIdx.x & 31, wid = threadIdx.x >> 5;
#pragma unroll
    for (int o = 16; o; o >>= 1) {
        s  += __shfl_xor_sync(0xffffffffu, s, o);
        ss += __shfl_xor_sync(0xffffffffu, ss, o);
    }
    if (lane == 0) { red0[wid] = s; red1[wid] = ss; }
    __syncthreads();
    if (threadIdx.x == 0) {
        float a = 0.f, c = 0.f;
#pragma unroll
        for (int i = 0; i < 8; i++) { a += red0[i]; c += red1[i]; }
        float mu = a * (1.0f / DMODEL);
        float var = c * (1.0f / DMODEL) - mu * mu;
        s_mu = mu;
        s_inv = rsqrtf(var + 1e-5f);
    }
    __syncthreads();
    float mu = s_mu, inv = s_inv;
    for (int d = threadIdx.x; d < DMODEL; d += 256)
        out[(size_t)t * DMODEL + d] = (row[d] - mu) * inv * w[d] + b[d];
}

// ---------------- fp16 tensor-core GEMM (legacy mma.sync, HMMA.16816) ----------------
// C[m][n] = sum_k A[m][k] * W[n][k]  (+bias, +epilogue). A:(M,K), W:(N,K) row-major fp32.
// Tile BM=128, BN=128, BK=32. 256 threads = 8 warps (4 M x 2 N). Warp tile 32x64 =
// 2 x 8 m16n8k16 tiles, fp32 accumulate.
// SMEM word layout off(k2,m) = (k2>>2)*512 + m*4 + (k2&3)   (k2 = k/2, half2 words):
//  - stores: per-thread 2 x STS.128 at consecutive words, warp covers all 32 banks
//  - fragment LDS.32: bank = (m%8)*4 + (k2%4), bijective over lanes -> conflict-free
// EPI: 0 = bias; 1 = bias + residual; 2 = bias + exact GELU

__device__ __forceinline__ uint32_t packh2(float lo, float hi) {
    __half2 h = __floats2half2_rn(lo, hi);
    return *reinterpret_cast<uint32_t*>(&h);
}

__device__ __forceinline__ void mma_f16(float* d, const uint32_t* a, const uint32_t* b) {
    asm volatile(
        "mma.sync.aligned.m16n8k16.row.col.f32.f16.f16.f32 "
        "{%0,%1,%2,%3}, {%4,%5,%6,%7}, {%8,%9}, {%0,%1,%2,%3};"
        : "+f"(d[0]), "+f"(d[1]), "+f"(d[2]), "+f"(d[3])
        : "r"(a[0]), "r"(a[1]), "r"(a[2]), "r"(a[3]), "r"(b[0]), "r"(b[1]));
}

template <int EPI>
__global__ void __launch_bounds__(256) gemm_f16(const float* __restrict__ A,
                                                const float* __restrict__ W,
                                                const float* __restrict__ bias,
                                                const float* __restrict__ res,
                                                float* __restrict__ C,
                                                int M, int N, int K) {
    __shared__ uint32_t Sa[2048];   // 8 KB: 128 rows x 16 half2 words
    __shared__ uint32_t Sw[2048];

    int tid = threadIdx.x;
    int m0 = blockIdx.y * 128, n0 = blockIdx.x * 128;
    int warp = tid >> 5, lane = tid & 31;
    int wm = warp & 3, wn = warp >> 2;
    int gid = lane >> 2, tig = lane & 3;

    float acc[2][8][4];
#pragma unroll
    for (int i = 0; i < 2; i++)
#pragma unroll
        for (int j = 0; j < 8; j++)
#pragma unroll
            for (int r = 0; r < 4; r++) acc[i][j][r] = 0.f;

    // global load mapping: r = tid&127 (row), hf = tid>>7 (k half: 16 fp32 each)
    int r = tid & 127, hf = tid >> 7;
    const float* Ap = A + (size_t)(m0 + r) * K + hf * 16;
    const float* Wp = W + (size_t)(n0 + r) * K + hf * 16;
    int sb0 = (2 * hf) * 512 + r * 4;        // word offset, k2 group 2hf
    int sb1 = (2 * hf + 1) * 512 + r * 4;    // k2 group 2hf+1

    int nch = K >> 5;    // K / 32
    float4 pa[4], pw[4];
#pragma unroll
    for (int j = 0; j < 4; j++) {
        pa[j] = *(const float4*)(Ap + j * 4);
        pw[j] = *(const float4*)(Wp + j * 4);
    }

    for (int c = 0; c < nch; c++) {
        __syncthreads();
        {
            uint4 lo = make_uint4(packh2(pa[0].x, pa[0].y), packh2(pa[0].z, pa[0].w),
                                  packh2(pa[1].x, pa[1].y), packh2(pa[1].z, pa[1].w));
            uint4 hi = make_uint4(packh2(pa[2].x, pa[2].y), packh2(pa[2].z, pa[2].w),
                                  packh2(pa[3].x, pa[3].y), packh2(pa[3].z, pa[3].w));
            *(uint4*)&Sa[sb0] = lo;
            *(uint4*)&Sa[sb1] = hi;
            lo = make_uint4(packh2(pw[0].x, pw[0].y), packh2(pw[0].z, pw[0].w),
                            packh2(pw[1].x, pw[1].y), packh2(pw[1].z, pw[1].w));
            hi = make_uint4(packh2(pw[2].x, pw[2].y), packh2(pw[2].z, pw[2].w),
                            packh2(pw[3].x, pw[3].y), packh2(pw[3].z, pw[3].w));
            *(uint4*)&Sw[sb0] = lo;
            *(uint4*)&Sw[sb1] = hi;
        }
        __syncthreads();

        if (c + 1 < nch) {
            const float* an = Ap + (c + 1) * 32;
            const float* wn_ = Wp + (c + 1) * 32;
#pragma unroll
            for (int j = 0; j < 4; j++) {
                pa[j] = *(const float4*)(an + j * 4);
                pw[j] = *(const float4*)(wn_ + j * 4);
            }
        }

#pragma unroll
        for (int s = 0; s < 2; s++) {            // two k16 steps
            int base = s * 1024;                 // (2s)*512
            uint32_t a[2][4], b[8][2];
#pragma unroll
            for (int i = 0; i < 2; i++) {
                int o = base + (wm * 32 + i * 16 + gid) * 4 + tig;
                a[i][0] = Sa[o];          // (m,    k2=s*8+tig)
                a[i][1] = Sa[o + 32];     // (m+8)
                a[i][2] = Sa[o + 512];    // (m,    k2+4)
                a[i][3] = Sa[o + 544];    // (m+8,  k2+4)
            }
#pragma unroll
            for (int j = 0; j < 8; j++) {
                int o = base + (wn * 64 + j * 8 + gid) * 4 + tig;
                b[j][0] = Sw[o];
                b[j][1] = Sw[o + 512];
            }
#pragma unroll
            for (int i = 0; i < 2; i++)
#pragma unroll
                for (int j = 0; j < 8; j++)
                    mma_f16(acc[i][j], a[i], b[j]);
        }
    }

    // epilogue (C layout of m16n8: c0,c1 = row gid cols 2t,2t+1; c2,c3 = row gid+8)
#pragma unroll
    for (int i = 0; i < 2; i++) {
        int mrow = m0 + wm * 32 + i * 16 + gid;
#pragma unroll
        for (int j = 0; j < 8; j++) {
            int n = n0 + wn * 64 + j * 8 + tig * 2;
            float bn0 = bias[n], bn1 = bias[n + 1];
#pragma unroll
            for (int h = 0; h < 2; h++) {
                int m = mrow + h * 8;
                float v0 = acc[i][j][h * 2 + 0] + bn0;
                float v1 = acc[i][j][h * 2 + 1] + bn1;
                if (EPI == 1) {
                    v0 += res[(size_t)m * N + n];
                    v1 += res[(size_t)m * N + n + 1];
                }
                if (EPI == 2) {
                    v0 = 0.5f * v0 * (1.0f + erff(v0 * 0.70710678118654752f));
                    v1 = 0.5f * v1 * (1.0f + erff(v1 * 0.70710678118654752f));
                }
                *(float2*)&C[(size_t)m * N + n] = make_float2(v0, v1);
            }
        }
    }
}

// ---------------- attention: SMEM-tiled, 8 warps share K/V chunks ----------------
// Block: 8 warps = 8 consecutive query rows of one (b,h). Chunk = 32 KV positions.
// Lane l scores position l via register dot; softmax stats via one shfl-reduce per
// chunk; P*V via shfl-broadcast FMAs (lane owns output dim d = lane).
__global__ void __launch_bounds__(256) attn_kernel(const float* __restrict__ qkv,
                                                   float* __restrict__ ctx) {
    __shared__ float Ks[32 * 33];
    __shared__ float Vs[32 * 33];

    int tid = threadIdx.x;
    int warp = tid >> 5, lane = tid & 31;
    int q0 = blockIdx.x * 8;
    int sq = q0 + warp;
    int bh = blockIdx.y;
    int b = bh / NHEAD, h = bh % NHEAD;

    // replicate q row into registers (broadcast LDG: all lanes same address)
    const float* qbase = qkv + ((size_t)sq * BATCH + b) * QKVDIM + h * 96;
    float q[32];
#pragma unroll
    for (int j = 0; j < 8; j++) {
        float4 v = *(const float4*)(qbase + j * 4);
        q[j * 4 + 0] = v.x * ATTN_SCALE;
        q[j * 4 + 1] = v.y * ATTN_SCALE;
        q[j * 4 + 2] = v.z * ATTN_SCALE;
        q[j * 4 + 3] = v.w * ATTN_SCALE;
    }

    float mmax = -1e30f, ssum = 0.f, acc0 = 0.f, acc1 = 0.f;

    int lr = tid >> 3, ls = tid & 7;      // load role: row 0..31, float4 slot 0..7
    int nc = (q0 + 8 + 31) >> 5;          // chunks covering rows <= q0+7

    for (int c = 0; c < nc; c++) {
        __syncthreads();
        {
            int kk = c * 32 + lr;
            float4 kv = make_float4(0.f, 0.f, 0.f, 0.f);
            float4 vv = make_float4(0.f, 0.f, 0.f, 0.f);
            if (kk < SEQ) {
                const float* rowp = qkv + ((size_t)kk * BATCH + b) * QKVDIM + h * 96;
                kv = *(const float4*)(rowp + 32 + ls * 4);
                vv = *(const float4*)(rowp + 64 + ls * 4);
            }
            int o = lr * 33 + ls * 4;
            Ks[o] = kv.x; Ks[o + 1] = kv.y; Ks[o + 2] = kv.z; Ks[o + 3] = kv.w;
            Vs[o] = vv.x; Vs[o + 1] = vv.y; Vs[o + 2] = vv.z; Vs[o + 3] = vv.w;
        }
        __syncthreads();

        int nvalid = sq - c * 32 + 1;     // lanes < nvalid are causally visible
        float s0 = 0.f, s1 = 0.f;
        const float* kr = &Ks[lane * 33];
#pragma unroll
        for (int d = 0; d < 32; d += 2) {
            s0 = fmaf(q[d], kr[d], s0);
            s1 = fmaf(q[d + 1], kr[d + 1], s1);
        }
        float s = (lane < nvalid) ? (s0 + s1) : -1e30f;

        float cm = s;
#pragma unroll
        for (int o = 16; o; o >>= 1) cm = fmaxf(cm, __shfl_xor_sync(0xffffffffu, cm, o));
        float mnew = fmaxf(mmax, cm);
        float p = __expf(s - mnew);
        float corr = __expf(mmax - mnew);
        mmax = mnew;

        float ps = p;
#pragma unroll
        for (int o = 16; o; o >>= 1) ps += __shfl_xor_sync(0xffffffffu, ps, o);
        ssum = ssum * corr + ps;

        acc0 *= corr;
        acc1 *= corr;
#pragma unroll
        for (int l = 0; l < 32; l += 2) {
            float p0 = __shfl_sync(0xffffffffu, p, l);
            float p1 = __shfl_sync(0xffffffffu, p, l + 1);
            acc0 = fmaf(p0, Vs[l * 33 + lane], acc0);
            acc1 = fmaf(p1, Vs[(l + 1) * 33 + lane], acc1);
        }
    }

    ctx[((size_t)sq * BATCH + b) * DMODEL + h * DHEAD + lane] = (acc0 + acc1) / ssum;
}

// ---------------- launch ----------------
struct LayerW {
    const float *ln1w, *ln1b, *wqkv, *bqkv, *wo, *bo, *ln2w, *ln2b, *wfc, *bfc, *wproj, *bproj;
};

extern "C" void kernel_launch(void* const* d_in, const int* in_sizes, int n_in,
                              void* d_out, int out_size) {
    const int*   ids  = (const int*)d_in[0];
    const int*   pos  = (const int*)d_in[1];
    const float* wte  = (const float*)d_in[3];
    const float* wpe  = (const float*)d_in[4];
    LayerW L[2];
    for (int l = 0; l < 2; l++) {
        int o = 5 + l * 12;
        L[l].ln1w  = (const float*)d_in[o + 0];
        L[l].ln1b  = (const float*)d_in[o + 1];
        L[l].wqkv  = (const float*)d_in[o + 2];
        L[l].bqkv  = (const float*)d_in[o + 3];
        L[l].wo    = (const float*)d_in[o + 4];
        L[l].bo    = (const float*)d_in[o + 5];
        L[l].ln2w  = (const float*)d_in[o + 6];
        L[l].ln2b  = (const float*)d_in[o + 7];
        L[l].wfc   = (const float*)d_in[o + 8];
        L[l].bfc   = (const float*)d_in[o + 9];
        L[l].wproj = (const float*)d_in[o + 10];
        L[l].bproj = (const float*)d_in[o + 11];
    }
    const float* lnfw = (const float*)d_in[29];
    const float* lnfb = (const float*)d_in[30];
    float* out = (float*)d_out;

    float* x   = nullptr;  cudaGetSymbolAddress((void**)&x,   g_x);
    float* h   = nullptr;  cudaGetSymbolAddress((void**)&h,   g_h);
    float* qkv = nullptr;  cudaGetSymbolAddress((void**)&qkv, g_qkv);
    float* ctx = nullptr;  cudaGetSymbolAddress((void**)&ctx, g_ctx);
    float* mbuf= nullptr;  cudaGetSymbolAddress((void**)&mbuf,g_m);

    embed_kernel<<<NTOK, 256>>>(ids, pos, wte, wpe, x);

    for (int l = 0; l < 2; l++) {
        ln_kernel<<<NTOK, 256>>>(x, L[l].ln1w, L[l].ln1b, h);
        {
            dim3 g(QKVDIM / 128, NTOK / 128);
            gemm_f16<0><<<g, 256>>>(h, L[l].wqkv, L[l].bqkv, nullptr, qkv, NTOK, QKVDIM, DMODEL);
        }
        {
            dim3 g(SEQ / 8, BATCH * NHEAD);
            attn_kernel<<<g, 256>>>(qkv, ctx);
        }
        {
            dim3 g(DMODEL / 128, NTOK / 128);
            gemm_f16<1><<<g, 256>>>(ctx, L[l].wo, L[l].bo, x, x, NTOK, DMODEL, DMODEL);
        }
        ln_kernel<<<NTOK, 256>>>(x, L[l].ln2w, L[l].ln2b, h);
        {
            dim3 g(FFDIM / 128, NTOK / 128);
            gemm_f16<2><<<g, 256>>>(h, L[l].wfc, L[l].bfc, nullptr, mbuf, NTOK, FFDIM, DMODEL);
        }
        {
            dim3 g(DMODEL / 128, NTOK / 128);
            gemm_f16<1><<<g, 256>>>(mbuf, L[l].wproj, L[l].bproj, x, x, NTOK, DMODEL, FFDIM);
        }
    }

    ln_kernel<<<NTOK, 256>>>(x, lnfw, lnfb, out);
    (void)in_sizes; (void)n_in; (void)out_size;
}

// round 9
// speedup vs baseline: 6.2611x; 1.9492x over previous
#include <cuda_runtime.h>
#include <cuda_fp16.h>
#include <cstdint>
#include <math.h>

// Problem constants
#define SEQ 1536
#define BATCH 2
#define DMODEL 768
#define NHEAD 24
#define DHEAD 32
#define FFDIM 3072
#define NTOK (SEQ * BATCH)
#define QKVDIM (3 * DMODEL)
#define ATTN_SCALE 0.17677669529663688f

// ---------------- scratch ----------------
__device__ float g_x[NTOK * DMODEL];
__device__ float g_h[NTOK * DMODEL];
__device__ float g_qkv[NTOK * QKVDIM];
__device__ float g_ctx[NTOK * DMODEL];
__device__ float g_m[NTOK * FFDIM];

__device__ __forceinline__ uint32_t packh2(float lo, float hi) {
    __half2 h = __floats2half2_rn(lo, hi);
    return *reinterpret_cast<uint32_t*>(&h);
}

__device__ __forceinline__ void mma_f16(float* d, const uint32_t* a, const uint32_t* b) {
    asm volatile(
        "mma.sync.aligned.m16n8k16.row.col.f32.f16.f16.f32 "
        "{%0,%1,%2,%3}, {%4,%5,%6,%7}, {%8,%9}, {%0,%1,%2,%3};"
        : "+f"(d[0]), "+f"(d[1]), "+f"(d[2]), "+f"(d[3])
        : "r"(a[0]), "r"(a[1]), "r"(a[2]), "r"(a[3]), "r"(b[0]), "r"(b[1]));
}

// ---------------- embedding ----------------
__global__ void embed_kernel(const int* __restrict__ ids, const int* __restrict__ pos,
                             const float* __restrict__ wte, const float* __restrict__ wpe,
                             float* __restrict__ x) {
    int t = blockIdx.x;
    int s = t / BATCH, b = t % BATCH;
    int id = ids[b * SEQ + s];
    int p  = pos[b * SEQ + s];
    const float* te = wte + (size_t)id * DMODEL;
    const float* pe = wpe + (size_t)p * DMODEL;
    for (int d = threadIdx.x; d < DMODEL; d += blockDim.x)
        x[(size_t)t * DMODEL + d] = te[d] + pe[d];
}

// ---------------- layernorm ----------------
__global__ void ln_kernel(const float* __restrict__ in, const float* __restrict__ w,
                          const float* __restrict__ b, float* __restrict__ out) {
    int t = blockIdx.x;
    const float* row = in + (size_t)t * DMODEL;
    float s = 0.f, ss = 0.f;
    for (int d = threadIdx.x; d < DMODEL; d += 256) {
        float v = row[d];
        s += v;
        ss = fmaf(v, v, ss);
    }
    __shared__ float red0[8], red1[8];
    __shared__ float s_mu, s_inv;
    int lane = threadIdx.x & 31, wid = threadIdx.x >> 5;
#pragma unroll
    for (int o = 16; o; o >>= 1) {
        s  += __shfl_xor_sync(0xffffffffu, s, o);
        ss += __shfl_xor_sync(0xffffffffu, ss, o);
    }
    if (lane == 0) { red0[wid] = s; red1[wid] = ss; }
    __syncthreads();
    if (threadIdx.x == 0) {
        float a = 0.f, c = 0.f;
#pragma unroll
        for (int i = 0; i < 8; i++) { a += red0[i]; c += red1[i]; }
        float mu = a * (1.0f / DMODEL);
        float var = c * (1.0f / DMODEL) - mu * mu;
        s_mu = mu;
        s_inv = rsqrtf(var + 1e-5f);
    }
    __syncthreads();
    float mu = s_mu, inv = s_inv;
    for (int d = threadIdx.x; d < DMODEL; d += 256)
        out[(size_t)t * DMODEL + d] = (row[d] - mu) * inv * w[d] + b[d];
}

// ---------------- fp16 tensor-core GEMM (unchanged from Round 8) ----------------
template <int EPI>
__global__ void __launch_bounds__(256) gemm_f16(const float* __restrict__ A,
                                                const float* __restrict__ W,
                                                const float* __restrict__ bias,
                                                const float* __restrict__ res,
                                                float* __restrict__ C,
                                                int M, int N, int K) {
    __shared__ uint32_t Sa[2048];
    __shared__ uint32_t Sw[2048];

    int tid = threadIdx.x;
    int m0 = blockIdx.y * 128, n0 = blockIdx.x * 128;
    int warp = tid >> 5, lane = tid & 31;
    int wm = warp & 3, wn = warp >> 2;
    int gid = lane >> 2, tig = lane & 3;

    float acc[2][8][4];
#pragma unroll
    for (int i = 0; i < 2; i++)
#pragma unroll
        for (int j = 0; j < 8; j++)
#pragma unroll
            for (int r = 0; r < 4; r++) acc[i][j][r] = 0.f;

    int r = tid & 127, hf = tid >> 7;
    const float* Ap = A + (size_t)(m0 + r) * K + hf * 16;
    const float* Wp = W + (size_t)(n0 + r) * K + hf * 16;
    int sb0 = (2 * hf) * 512 + r * 4;
    int sb1 = (2 * hf + 1) * 512 + r * 4;

    int nch = K >> 5;
    float4 pa[4], pw[4];
#pragma unroll
    for (int j = 0; j < 4; j++) {
        pa[j] = *(const float4*)(Ap + j * 4);
        pw[j] = *(const float4*)(Wp + j * 4);
    }

    for (int c = 0; c < nch; c++) {
        __syncthreads();
        {
            uint4 lo = make_uint4(packh2(pa[0].x, pa[0].y), packh2(pa[0].z, pa[0].w),
                                  packh2(pa[1].x, pa[1].y), packh2(pa[1].z, pa[1].w));
            uint4 hi = make_uint4(packh2(pa[2].x, pa[2].y), packh2(pa[2].z, pa[2].w),
                                  packh2(pa[3].x, pa[3].y), packh2(pa[3].z, pa[3].w));
            *(uint4*)&Sa[sb0] = lo;
            *(uint4*)&Sa[sb1] = hi;
            lo = make_uint4(packh2(pw[0].x, pw[0].y), packh2(pw[0].z, pw[0].w),
                            packh2(pw[1].x, pw[1].y), packh2(pw[1].z, pw[1].w));
            hi = make_uint4(packh2(pw[2].x, pw[2].y), packh2(pw[2].z, pw[2].w),
                            packh2(pw[3].x, pw[3].y), packh2(pw[3].z, pw[3].w));
            *(uint4*)&Sw[sb0] = lo;
            *(uint4*)&Sw[sb1] = hi;
        }
        __syncthreads();

        if (c + 1 < nch) {
            const float* an = Ap + (c + 1) * 32;
            const float* wn_ = Wp + (c + 1) * 32;
#pragma unroll
            for (int j = 0; j < 4; j++) {
                pa[j] = *(const float4*)(an + j * 4);
                pw[j] = *(const float4*)(wn_ + j * 4);
            }
        }

#pragma unroll
        for (int s = 0; s < 2; s++) {
            int base = s * 1024;
            uint32_t a[2][4], b[8][2];
#pragma unroll
            for (int i = 0; i < 2; i++) {
                int o = base + (wm * 32 + i * 16 + gid) * 4 + tig;
                a[i][0] = Sa[o];
                a[i][1] = Sa[o + 32];
                a[i][2] = Sa[o + 512];
                a[i][3] = Sa[o + 544];
            }
#pragma unroll
            for (int j = 0; j < 8; j++) {
                int o = base + (wn * 64 + j * 8 + gid) * 4 + tig;
                b[j][0] = Sw[o];
                b[j][1] = Sw[o + 512];
            }
#pragma unroll
            for (int i = 0; i < 2; i++)
#pragma unroll
                for (int j = 0; j < 8; j++)
                    mma_f16(acc[i][j], a[i], b[j]);
        }
    }

#pragma unroll
    for (int i = 0; i < 2; i++) {
        int mrow = m0 + wm * 32 + i * 16 + gid;
#pragma unroll
        for (int j = 0; j < 8; j++) {
            int n = n0 + wn * 64 + j * 8 + tig * 2;
            float bn0 = bias[n], bn1 = bias[n + 1];
#pragma unroll
            for (int h = 0; h < 2; h++) {
                int m = mrow + h * 8;
                float v0 = acc[i][j][h * 2 + 0] + bn0;
                float v1 = acc[i][j][h * 2 + 1] + bn1;
                if (EPI == 1) {
                    v0 += res[(size_t)m * N + n];
                    v1 += res[(size_t)m * N + n + 1];
                }
                if (EPI == 2) {
                    v0 = 0.5f * v0 * (1.0f + erff(v0 * 0.70710678118654752f));
                    v1 = 0.5f * v1 * (1.0f + erff(v1 * 0.70710678118654752f));
                }
                *(float2*)&C[(size_t)m * N + n] = make_float2(v0, v1);
            }
        }
    }
}

// ---------------- flash attention with fp16 mma ----------------
// Block = 64 queries x one (b,h). 4 warps, warp w owns rows q0+16w .. +15.
// KV tile = 64. QK^T: A = Q frags (regs), B = K in smem. Softmax in registers.
// P·V: QK C-fragment layout == A-fragment layout -> zero-cost P reuse.
// V stored transposed (half2 along kv). Strides 36 words -> conflict-free frags.
#define SKW 36
__global__ void __launch_bounds__(128) attn_mma(const float* __restrict__ qkv,
                                                float* __restrict__ ctx) {
    __shared__ uint32_t Ks[64 * SKW];   // [kv][dh-pair 0..15]
    __shared__ uint32_t Vt[32 * SKW];   // [dh][kv-pair 0..31]

    int tid = threadIdx.x;
    int warp = tid >> 5, lane = tid & 31;
    int gid = lane >> 2, tig = lane & 3;
    int qb = gridDim.x - 1 - blockIdx.x;        // big blocks first
    int q0 = qb * 64;
    int bh = blockIdx.y;
    int b = bh / NHEAD, h = bh % NHEAD;

    int row_lo = q0 + warp * 16 + gid;          // absolute query row (lo half)

    // Q fragments, pre-scaled
    uint32_t aq[2][4];
    {
        const float* qlo = qkv + ((size_t)row_lo * BATCH + b) * QKVDIM + h * 96;
        const float* qhi = qlo + (size_t)8 * BATCH * QKVDIM;
#pragma unroll
        for (int ks = 0; ks < 2; ks++) {
            int d0 = ks * 16 + 2 * tig;
            float2 v;
            v = *(const float2*)(qlo + d0);
            aq[ks][0] = packh2(v.x * ATTN_SCALE, v.y * ATTN_SCALE);
            v = *(const float2*)(qhi + d0);
            aq[ks][1] = packh2(v.x * ATTN_SCALE, v.y * ATTN_SCALE);
            v = *(const float2*)(qlo + d0 + 8);
            aq[ks][2] = packh2(v.x * ATTN_SCALE, v.y * ATTN_SCALE);
            v = *(const float2*)(qhi + d0 + 8);
            aq[ks][3] = packh2(v.x * ATTN_SCALE, v.y * ATTN_SCALE);
        }
    }

    float m_lo = -1e30f, m_hi = -1e30f, l_lo = 0.f, l_hi = 0.f;
    float O[4][4];
#pragma unroll
    for (int j = 0; j < 4; j++)
#pragma unroll
        for (int r = 0; r < 4; r++) O[j][r] = 0.f;

    for (int kb = 0; kb <= qb; kb++) {
        __syncthreads();
        // K tile: 64 rows x 16 half2 words
#pragma unroll
        for (int i = 0; i < 8; i++) {
            int idx = tid + i * 128;
            int kv = idx >> 4, w = idx & 15;
            const float* kr = qkv + ((size_t)(kb * 64 + kv) * BATCH + b) * QKVDIM + h * 96 + 32 + 2 * w;
            float2 v = *(const float2*)kr;
            Ks[kv * SKW + w] = packh2(v.x, v.y);
        }
        // V^T tile: 32 dh x 32 kv-pair words
#pragma unroll
        for (int i = 0; i < 8; i++) {
            int idx = tid + i * 128;
            int dh = idx >> 5, kvw = idx & 31;
            const float* v0 = qkv + ((size_t)(kb * 64 + 2 * kvw) * BATCH + b) * QKVDIM + h * 96 + 64 + dh;
            float a = *v0;
            float c = *(v0 + (size_t)BATCH * QKVDIM);
            Vt[dh * SKW + kvw] = packh2(a, c);
        }
        __syncthreads();

        // scores: 8 n-tiles x (2 rows x 2 cols)
        float sc[8][4];
#pragma unroll
        for (int j = 0; j < 8; j++) {
            sc[j][0] = sc[j][1] = sc[j][2] = sc[j][3] = 0.f;
#pragma unroll
            for (int ks = 0; ks < 2; ks++) {
                uint32_t bb[2];
                int o = (j * 8 + gid) * SKW + ks * 8 + tig;
                bb[0] = Ks[o];
                bb[1] = Ks[o + 4];
                mma_f16(sc[j], aq[ks], bb);
            }
        }

        if (kb == qb) {   // diagonal tile: causal mask
            int rl = warp * 16 + gid, rh = rl + 8;
#pragma unroll
            for (int j = 0; j < 8; j++) {
                int c0 = j * 8 + 2 * tig, c1 = c0 + 1;
                if (c0 > rl) sc[j][0] = -1e30f;
                if (c1 > rl) sc[j][1] = -1e30f;
                if (c0 > rh) sc[j][2] = -1e30f;
                if (c1 > rh) sc[j][3] = -1e30f;
            }
        }

        // online softmax
        float mt_lo = -1e30f, mt_hi = -1e30f;
#pragma unroll
        for (int j = 0; j < 8; j++) {
            mt_lo = fmaxf(mt_lo, fmaxf(sc[j][0], sc[j][1]));
            mt_hi = fmaxf(mt_hi, fmaxf(sc[j][2], sc[j][3]));
        }
        mt_lo = fmaxf(mt_lo, __shfl_xor_sync(0xffffffffu, mt_lo, 1));
        mt_lo = fmaxf(mt_lo, __shfl_xor_sync(0xffffffffu, mt_lo, 2));
        mt_hi = fmaxf(mt_hi, __shfl_xor_sync(0xffffffffu, mt_hi, 1));
        mt_hi = fmaxf(mt_hi, __shfl_xor_sync(0xffffffffu, mt_hi, 2));

        float mn_lo = fmaxf(m_lo, mt_lo), mn_hi = fmaxf(m_hi, mt_hi);
        float corr_lo = __expf(m_lo - mn_lo), corr_hi = __expf(m_hi - mn_hi);
        m_lo = mn_lo;
        m_hi = mn_hi;

        uint32_t pp[8][2];
        float rs_lo = 0.f, rs_hi = 0.f;
#pragma unroll
        for (int j = 0; j < 8; j++) {
            float p0 = __expf(sc[j][0] - mn_lo);
            float p1 = __expf(sc[j][1] - mn_lo);
            float p2 = __expf(sc[j][2] - mn_hi);
            float p3 = __expf(sc[j][3] - mn_hi);
            rs_lo += p0 + p1;
            rs_hi += p2 + p3;
            pp[j][0] = packh2(p0, p1);
            pp[j][1] = packh2(p2, p3);
        }
        rs_lo += __shfl_xor_sync(0xffffffffu, rs_lo, 1);
        rs_lo += __shfl_xor_sync(0xffffffffu, rs_lo, 2);
        rs_hi += __shfl_xor_sync(0xffffffffu, rs_hi, 1);
        rs_hi += __shfl_xor_sync(0xffffffffu, rs_hi, 2);
        l_lo = l_lo * corr_lo + rs_lo;
        l_hi = l_hi * corr_hi + rs_hi;

#pragma unroll
        for (int j = 0; j < 4; j++) {
            O[j][0] *= corr_lo; O[j][1] *= corr_lo;
            O[j][2] *= corr_hi; O[j][3] *= corr_hi;
        }

        // P·V: 4 ksteps (16 kv each) x 4 n-tiles (8 dh each)
#pragma unroll
        for (int ks = 0; ks < 4; ks++) {
            uint32_t ap[4] = {pp[2 * ks][0], pp[2 * ks][1], pp[2 * ks + 1][0], pp[2 * ks + 1][1]};
#pragma unroll
            for (int jn = 0; jn < 4; jn++) {
                uint32_t bb[2];
                int o = (jn * 8 + gid) * SKW + ks * 8 + tig;
                bb[0] = Vt[o];
                bb[1] = Vt[o + 4];
                mma_f16(O[jn], ap, bb);
            }
        }
    }

    // write out
    float inv_lo = 1.f / l_lo, inv_hi = 1.f / l_hi;
    float* crow_lo = ctx + ((size_t)row_lo * BATCH + b) * DMODEL + h * 32;
    float* crow_hi = crow_lo + (size_t)8 * BATCH * DMODEL;
#pragma unroll
    for (int jn = 0; jn < 4; jn++) {
        int d = jn * 8 + 2 * tig;
        *(float2*)(crow_lo + d) = make_float2(O[jn][0] * inv_lo, O[jn][1] * inv_lo);
        *(float2*)(crow_hi + d) = make_float2(O[jn][2] * inv_hi, O[jn][3] * inv_hi);
    }
}

// ---------------- launch ----------------
struct LayerW {
    const float *ln1w, *ln1b, *wqkv, *bqkv, *wo, *bo, *ln2w, *ln2b, *wfc, *bfc, *wproj, *bproj;
};

extern "C" void kernel_launch(void* const* d_in, const int* in_sizes, int n_in,
                              void* d_out, int out_size) {
    const int*   ids  = (const int*)d_in[0];
    const int*   pos  = (const int*)d_in[1];
    const float* wte  = (const float*)d_in[3];
    const float* wpe  = (const float*)d_in[4];
    LayerW L[2];
    for (int l = 0; l < 2; l++) {
        int o = 5 + l * 12;
        L[l].ln1w  = (const float*)d_in[o + 0];
        L[l].ln1b  = (const float*)d_in[o + 1];
        L[l].wqkv  = (const float*)d_in[o + 2];
        L[l].bqkv  = (const float*)d_in[o + 3];
        L[l].wo    = (const float*)d_in[o + 4];
        L[l].bo    = (const float*)d_in[o + 5];
        L[l].ln2w  = (const float*)d_in[o + 6];
        L[l].ln2b  = (const float*)d_in[o + 7];
        L[l].wfc   = (const float*)d_in[o + 8];
        L[l].bfc   = (const float*)d_in[o + 9];
        L[l].wproj = (const float*)d_in[o + 10];
        L[l].bproj = (const float*)d_in[o + 11];
    }
    const float* lnfw = (const float*)d_in[29];
    const float* lnfb = (const float*)d_in[30];
    float* out = (float*)d_out;

    float* x   = nullptr;  cudaGetSymbolAddress((void**)&x,   g_x);
    float* h   = nullptr;  cudaGetSymbolAddress((void**)&h,   g_h);
    float* qkv = nullptr;  cudaGetSymbolAddress((void**)&qkv, g_qkv);
    float* ctx = nullptr;  cudaGetSymbolAddress((void**)&ctx, g_ctx);
    float* mbuf= nullptr;  cudaGetSymbolAddress((void**)&mbuf,g_m);

    embed_kernel<<<NTOK, 256>>>(ids, pos, wte, wpe, x);

    for (int l = 0; l < 2; l++) {
        ln_kernel<<<NTOK, 256>>>(x, L[l].ln1w, L[l].ln1b, h);
        {
            dim3 g(QKVDIM / 128, NTOK / 128);
            gemm_f16<0><<<g, 256>>>(h, L[l].wqkv, L[l].bqkv, nullptr, qkv, NTOK, QKVDIM, DMODEL);
        }
        {
            dim3 g(SEQ / 64, BATCH * NHEAD);
            attn_mma<<<g, 128>>>(qkv, ctx);
        }
        {
            dim3 g(DMODEL / 128, NTOK / 128);
            gemm_f16<1><<<g, 256>>>(ctx, L[l].wo, L[l].bo, x, x, NTOK, DMODEL, DMODEL);
        }
        ln_kernel<<<NTOK, 256>>>(x, L[l].ln2w, L[l].ln2b, h);
        {
            dim3 g(FFDIM / 128, NTOK / 128);
            gemm_f16<2><<<g, 256>>>(h, L[l].wfc, L[l].bfc, nullptr, mbuf, NTOK, FFDIM, DMODEL);
        }
        {
            dim3 g(DMODEL / 128, NTOK / 128);
            gemm_f16<1><<<g, 256>>>(mbuf, L[l].wproj, L[l].bproj, x, x, NTOK, DMODEL, FFDIM);
        }
    }

    ln_kernel<<<NTOK, 256>>>(x, lnfw, lnfb, out);
    (void)in_sizes; (void)n_in; (void)out_size;
}

// round 16
// speedup vs baseline: 10.3468x; 1.6525x over previous
#include <cuda_runtime.h>
#include <cuda_fp16.h>
#include <cstdint>
#include <math.h>

// Problem constants
#define SEQ 1536
#define BATCH 2
#define DMODEL 768
#define NHEAD 24
#define DHEAD 32
#define FFDIM 3072
#define NTOK (SEQ * BATCH)
#define QKVDIM (3 * DMODEL)
#define ATTN_SCALE 0.17677669529663688f
#define HSIZE (BATCH * NHEAD * SEQ * DHEAD)

// ---------------- scratch ----------------
__device__ float  g_x[NTOK * DMODEL];        // residual stream fp32
__device__ __half g_hh[NTOK * DMODEL];       // LN out (half)
__device__ __half g_wh[FFDIM * DMODEL];      // converted weight (half), reused
__device__ __half g_qh[HSIZE];               // Q pre-scaled  [b][h][s][dh]
__device__ __half g_kh[HSIZE];               // K             [b][h][s][dh]
__device__ __half g_vt[HSIZE];               // V transposed  [b][h][dh][s]
__device__ __half g_ctxh[NTOK * DMODEL];     // attention out (half)
__device__ __half g_mh[NTOK * FFDIM];        // gelu out (half)

__device__ __forceinline__ uint32_t packh2(float lo, float hi) {
    __half2 h = __floats2half2_rn(lo, hi);
    return *reinterpret_cast<uint32_t*>(&h);
}

__device__ __forceinline__ void mma_f16(float* d, const uint32_t* a, const uint32_t* b) {
    asm volatile(
        "mma.sync.aligned.m16n8k16.row.col.f32.f16.f16.f32 "
        "{%0,%1,%2,%3}, {%4,%5,%6,%7}, {%8,%9}, {%0,%1,%2,%3};"
        : "+f"(d[0]), "+f"(d[1]), "+f"(d[2]), "+f"(d[3])
        : "r"(a[0]), "r"(a[1]), "r"(a[2]), "r"(a[3]), "r"(b[0]), "r"(b[1]));
}

// ---------------- fp32 -> half convert (weights) ----------------
__global__ void cvt_half_kernel(const float* __restrict__ in, __half* __restrict__ out, int n) {
    int i = (blockIdx.x * 256 + threadIdx.x) * 8;
    if (i >= n) return;
    float4 a = *(const float4*)(in + i);
    float4 b = *(const float4*)(in + i + 4);
    uint4 u = make_uint4(packh2(a.x, a.y), packh2(a.z, a.w), packh2(b.x, b.y), packh2(b.z, b.w));
    *(uint4*)(out + i) = u;
}

// ---------------- embedding ----------------
__global__ void embed_kernel(const int* __restrict__ ids, const int* __restrict__ pos,
                             const float* __restrict__ wte, const float* __restrict__ wpe,
                             float* __restrict__ x) {
    int t = blockIdx.x;
    int s = t / BATCH, b = t % BATCH;
    int id = ids[b * SEQ + s];
    int p  = pos[b * SEQ + s];
    const float* te = wte + (size_t)id * DMODEL;
    const float* pe = wpe + (size_t)p * DMODEL;
    for (int d = threadIdx.x; d < DMODEL; d += blockDim.x)
        x[(size_t)t * DMODEL + d] = te[d] + pe[d];
}

// ---------------- layernorm (OUT_HALF: write half buffer, else fp32) ----------------
template <int OUT_HALF>
__global__ void ln_kernel(const float* __restrict__ in, const float* __restrict__ w,
                          const float* __restrict__ b, float* __restrict__ outf,
                          __half* __restrict__ outh) {
    int t = blockIdx.x;
    const float* row = in + (size_t)t * DMODEL;
    float s = 0.f, ss = 0.f;
    for (int d = threadIdx.x; d < DMODEL; d += 256) {
        float v = row[d];
        s += v;
        ss = fmaf(v, v, ss);
    }
    __shared__ float red0[8], red1[8];
    __shared__ float s_mu, s_inv;
    int lane = threadIdx.x & 31, wid = threadIdx.x >> 5;
#pragma unroll
    for (int o = 16; o; o >>= 1) {
        s  += __shfl_xor_sync(0xffffffffu, s, o);
        ss += __shfl_xor_sync(0xffffffffu, ss, o);
    }
    if (lane == 0) { red0[wid] = s; red1[wid] = ss; }
    __syncthreads();
    if (threadIdx.x == 0) {
        float a = 0.f, c = 0.f;
#pragma unroll
        for (int i = 0; i < 8; i++) { a += red0[i]; c += red1[i]; }
        float mu = a * (1.0f / DMODEL);
        float var = c * (1.0f / DMODEL) - mu * mu;
        s_mu = mu;
        s_inv = rsqrtf(var + 1e-5f);
    }
    __syncthreads();
    float mu = s_mu, inv = s_inv;
    for (int d = threadIdx.x; d < DMODEL; d += 256) {
        float v = (row[d] - mu) * inv * w[d] + b[d];
        if (OUT_HALF) outh[(size_t)t * DMODEL + d] = __float2half(v);
        else          outf[(size_t)t * DMODEL + d] = v;
    }
}

// ---------------- half-input tensor-core GEMM, double-buffered ----------------
// C = A @ W^T + bias (+epilogue). A:(M,K) half, W:(N,K) half, row-major.
// BM=BN=128, BK=32, 8 warps (4Mx2N), warp tile 32x64 = 2x8 m16n8k16, fp32 accum.
// SMEM word layout off(k2,m) = (k2>>2)*512 + m*4 + (k2&3).
// Thread (r, hf) stages halves [hf*16, hf*16+16): first uint4 (k2 grp 2hf) at
// sb0 = (2hf)*512 + r*4, second uint4 (k2 grp 2hf+1) at sb1 = sb0 + 512.
// EPI: 0 = qkv-scatter (q scaled, k rows, v transposed)
//      1 = bias + residual -> fp32
//      2 = bias + exact GELU -> half
template <int EPI>
__global__ void __launch_bounds__(256) gemm_h(const __half* __restrict__ A,
                                              const __half* __restrict__ W,
                                              const float* __restrict__ bias,
                                              const float* __restrict__ res,
                                              float* __restrict__ Cf,
                                              __half* __restrict__ Ch,
                                              __half* __restrict__ qh,
                                              __half* __restrict__ kh,
                                              __half* __restrict__ vt,
                                              int M, int N, int K) {
    __shared__ uint32_t Sa[2 * 2048];
    __shared__ uint32_t Sw[2 * 2048];

    int tid = threadIdx.x;
    int m0 = blockIdx.y * 128, n0 = blockIdx.x * 128;
    int warp = tid >> 5, lane = tid & 31;
    int wm = warp & 3, wn = warp >> 2;
    int gid = lane >> 2, tig = lane & 3;

    float acc[2][8][4];
#pragma unroll
    for (int i = 0; i < 2; i++)
#pragma unroll
        for (int j = 0; j < 8; j++)
#pragma unroll
            for (int r = 0; r < 4; r++) acc[i][j][r] = 0.f;

    // loads: r = row (0..127), hf = which 16-half group of the 32-half chunk
    int r = tid & 127, hf = tid >> 7;
    const __half* Ap = A + (size_t)(m0 + r) * K + hf * 16;
    const __half* Wp = W + (size_t)(n0 + r) * K + hf * 16;
    int sb0 = (2 * hf) * 512 + r * 4;
    int sb1 = sb0 + 512;                 // k2 group 2hf+1 lives +512 words

    int nch = K >> 5;
    uint4 pa0 = *(const uint4*)Ap;
    uint4 pa1 = *(const uint4*)(Ap + 8);
    uint4 pw0 = *(const uint4*)Wp;
    uint4 pw1 = *(const uint4*)(Wp + 8);
    // prologue: stage chunk 0 into buffer 0
    *(uint4*)&Sa[sb0] = pa0;  *(uint4*)&Sa[sb1] = pa1;
    *(uint4*)&Sw[sb0] = pw0;  *(uint4*)&Sw[sb1] = pw1;

    for (int c = 0; c < nch; c++) {
        __syncthreads();                     // buffer c&1 ready
        if (c + 1 < nch) {
            const __half* an = Ap + (size_t)(c + 1) * 32;
            const __half* wn_ = Wp + (size_t)(c + 1) * 32;
            pa0 = *(const uint4*)an;  pa1 = *(const uint4*)(an + 8);
            pw0 = *(const uint4*)wn_; pw1 = *(const uint4*)(wn_ + 8);
        }
        int bo = (c & 1) * 2048;
#pragma unroll
        for (int s = 0; s < 2; s++) {
            int base = bo + s * 1024;
            uint32_t a[2][4], b[8][2];
#pragma unroll
            for (int i = 0; i < 2; i++) {
                int o = base + (wm * 32 + i * 16 + gid) * 4 + tig;
                a[i][0] = Sa[o];
                a[i][1] = Sa[o + 32];
                a[i][2] = Sa[o + 512];
                a[i][3] = Sa[o + 544];
            }
#pragma unroll
            for (int j = 0; j < 8; j++) {
                int o = base + (wn * 64 + j * 8 + gid) * 4 + tig;
                b[j][0] = Sw[o];
                b[j][1] = Sw[o + 512];
            }
#pragma unroll
            for (int i = 0; i < 2; i++)
#pragma unroll
                for (int j = 0; j < 8; j++)
                    mma_f16(acc[i][j], a[i], b[j]);
        }
        if (c + 1 < nch) {
            int nb = ((c + 1) & 1) * 2048;
            *(uint4*)&Sa[nb + sb0] = pa0;  *(uint4*)&Sa[nb + sb1] = pa1;
            *(uint4*)&Sw[nb + sb0] = pw0;  *(uint4*)&Sw[nb + sb1] = pw1;
        }
    }

    // epilogue
#pragma unroll
    for (int i = 0; i < 2; i++) {
        int mrow = m0 + wm * 32 + i * 16 + gid;
#pragma unroll
        for (int j = 0; j < 8; j++) {
            int n = n0 + wn * 64 + j * 8 + tig * 2;
            float bn0 = bias[n], bn1 = bias[n + 1];
#pragma unroll
            for (int hh = 0; hh < 2; hh++) {
                int m = mrow + hh * 8;
                float v0 = acc[i][j][hh * 2 + 0] + bn0;
                float v1 = acc[i][j][hh * 2 + 1] + bn1;
                if (EPI == 0) {
                    // qkv scatter: m = s*BATCH+b ; n -> head, component
                    int s = m >> 1, bb = m & 1;
                    int hd = n / 96, c = n % 96;
                    size_t hb = (size_t)(bb * NHEAD + hd);
                    if (c < 32) {
                        *(uint32_t*)(qh + (hb * SEQ + s) * 32 + c) =
                            packh2(v0 * ATTN_SCALE, v1 * ATTN_SCALE);
                    } else if (c < 64) {
                        *(uint32_t*)(kh + (hb * SEQ + s) * 32 + (c - 32)) = packh2(v0, v1);
                    } else {
                        vt[(hb * 32 + (c - 64)) * SEQ + s] = __float2half(v0);
                        vt[(hb * 32 + (c - 63)) * SEQ + s] = __float2half(v1);
                    }
                } else if (EPI == 1) {
                    v0 += res[(size_t)m * N + n];
                    v1 += res[(size_t)m * N + n + 1];
                    *(float2*)&Cf[(size_t)m * N + n] = make_float2(v0, v1);
                } else {
                    v0 = 0.5f * v0 * (1.0f + erff(v0 * 0.70710678118654752f));
                    v1 = 0.5f * v1 * (1.0f + erff(v1 * 0.70710678118654752f));
                    *(uint32_t*)(Ch + (size_t)m * N + n) = packh2(v0, v1);
                }
            }
        }
    }
}

// ---------------- flash attention, half inputs, double-buffered tiles ----------------
#define SKW 36
#define KTW (64 * SKW)    // K tile words
#define VTW (32 * SKW)    // V tile words
__global__ void __launch_bounds__(128) attn_mma(const __half* __restrict__ qh,
                                                const __half* __restrict__ kh,
                                                const __half* __restrict__ vt,
                                                __half* __restrict__ ctxh) {
    __shared__ uint32_t Ks[2 * KTW];
    __shared__ uint32_t Vt[2 * VTW];

    int tid = threadIdx.x;
    int warp = tid >> 5, lane = tid & 31;
    int gid = lane >> 2, tig = lane & 3;
    int qb = gridDim.x - 1 - blockIdx.x;       // big blocks first
    int q0 = qb * 64;
    int bh = blockIdx.y;
    int b = bh / NHEAD, h = bh % NHEAD;
    size_t hb = (size_t)(b * NHEAD + h);

    const __half* khh = kh + hb * SEQ * 32;
    const __half* vth = vt + hb * 32 * SEQ;

    int row_lo = q0 + warp * 16 + gid;

    // Q fragments (pre-scaled in qkv epilogue): direct uint32 loads
    uint32_t aq[2][4];
    {
        const __half* qlo = qh + (hb * SEQ + row_lo) * 32;
        const __half* qhi = qlo + 8 * 32;
#pragma unroll
        for (int ks = 0; ks < 2; ks++) {
            int d0 = ks * 16 + 2 * tig;
            aq[ks][0] = *(const uint32_t*)(qlo + d0);
            aq[ks][1] = *(const uint32_t*)(qhi + d0);
            aq[ks][2] = *(const uint32_t*)(qlo + d0 + 8);
            aq[ks][3] = *(const uint32_t*)(qhi + d0 + 8);
        }
    }

    float m_lo = -1e30f, m_hi = -1e30f, l_lo = 0.f, l_hi = 0.f;
    float O[4][4];
#pragma unroll
    for (int j = 0; j < 4; j++)
#pragma unroll
        for (int r = 0; r < 4; r++) O[j][r] = 0.f;

    // copy roles
    int kv = tid >> 1, hfk = tid & 1;          // K: row, 16-half group
    int dh = tid >> 2, qv = tid & 3;           // V: dh row, 16-half group along kv

    // prologue: tile 0 -> buffer 0
    {
        const __half* kr = khh + (size_t)kv * 32 + hfk * 16;
        uint4 k0 = *(const uint4*)kr;
        uint4 k1 = *(const uint4*)(kr + 8);
        *(uint4*)&Ks[kv * SKW + hfk * 8]     = k0;
        *(uint4*)&Ks[kv * SKW + hfk * 8 + 4] = k1;
        const __half* vr = vth + (size_t)dh * SEQ + qv * 16;
        uint4 v0 = *(const uint4*)vr;
        uint4 v1 = *(const uint4*)(vr + 8);
        *(uint4*)&Vt[dh * SKW + qv * 8]     = v0;
        *(uint4*)&Vt[dh * SKW + qv * 8 + 4] = v1;
    }

    for (int kb = 0; kb <= qb; kb++) {
        __syncthreads();                       // buffer kb&1 ready
        uint4 pk0, pk1, pv0, pv1;
        if (kb < qb) {
            const __half* kr = khh + (size_t)((kb + 1) * 64 + kv) * 32 + hfk * 16;
            pk0 = *(const uint4*)kr;
            pk1 = *(const uint4*)(kr + 8);
            const __half* vr = vth + (size_t)dh * SEQ + (kb + 1) * 64 + qv * 16;
            pv0 = *(const uint4*)vr;
            pv1 = *(const uint4*)(vr + 8);
        }
        int kbase = (kb & 1) * KTW, vbase = (kb & 1) * VTW;

        // scores
        float sc[8][4];
#pragma unroll
        for (int j = 0; j < 8; j++) {
            sc[j][0] = sc[j][1] = sc[j][2] = sc[j][3] = 0.f;
#pragma unroll
            for (int ks = 0; ks < 2; ks++) {
                uint32_t bb[2];
                int o = kbase + (j * 8 + gid) * SKW + ks * 8 + tig;
                bb[0] = Ks[o];
                bb[1] = Ks[o + 4];
                mma_f16(sc[j], aq[ks], bb);
            }
        }

        if (kb == qb) {   // causal mask on diagonal tile
            int rl = warp * 16 + gid, rh = rl + 8;
#pragma unroll
            for (int j = 0; j < 8; j++) {
                int c0 = j * 8 + 2 * tig, c1 = c0 + 1;
                if (c0 > rl) sc[j][0] = -1e30f;
                if (c1 > rl) sc[j][1] = -1e30f;
                if (c0 > rh) sc[j][2] = -1e30f;
                if (c1 > rh) sc[j][3] = -1e30f;
            }
        }

        // online softmax
        float mt_lo = -1e30f, mt_hi = -1e30f;
#pragma unroll
        for (int j = 0; j < 8; j++) {
            mt_lo = fmaxf(mt_lo, fmaxf(sc[j][0], sc[j][1]));
            mt_hi = fmaxf(mt_hi, fmaxf(sc[j][2], sc[j][3]));
        }
        mt_lo = fmaxf(mt_lo, __shfl_xor_sync(0xffffffffu, mt_lo, 1));
        mt_lo = fmaxf(mt_lo, __shfl_xor_sync(0xffffffffu, mt_lo, 2));
        mt_hi = fmaxf(mt_hi, __shfl_xor_sync(0xffffffffu, mt_hi, 1));
        mt_hi = fmaxf(mt_hi, __shfl_xor_sync(0xffffffffu, mt_hi, 2));

        float mn_lo = fmaxf(m_lo, mt_lo), mn_hi = fmaxf(m_hi, mt_hi);
        float corr_lo = __expf(m_lo - mn_lo), corr_hi = __expf(m_hi - mn_hi);
        m_lo = mn_lo;
        m_hi = mn_hi;

        uint32_t pp[8][2];
        float rs_lo = 0.f, rs_hi = 0.f;
#pragma unroll
        for (int j = 0; j < 8; j++) {
            float p0 = __expf(sc[j][0] - mn_lo);
            float p1 = __expf(sc[j][1] - mn_lo);
            float p2 = __expf(sc[j][2] - mn_hi);
            float p3 = __expf(sc[j][3] - mn_hi);
            rs_lo += p0 + p1;
            rs_hi += p2 + p3;
            pp[j][0] = packh2(p0, p1);
            pp[j][1] = packh2(p2, p3);
        }
        rs_lo += __shfl_xor_sync(0xffffffffu, rs_lo, 1);
        rs_lo += __shfl_xor_sync(0xffffffffu, rs_lo, 2);
        rs_hi += __shfl_xor_sync(0xffffffffu, rs_hi, 1);
        rs_hi += __shfl_xor_sync(0xffffffffu, rs_hi, 2);
        l_lo = l_lo * corr_lo + rs_lo;
        l_hi = l_hi * corr_hi + rs_hi;

#pragma unroll
        for (int j = 0; j < 4; j++) {
            O[j][0] *= corr_lo; O[j][1] *= corr_lo;
            O[j][2] *= corr_hi; O[j][3] *= corr_hi;
        }

        // P·V
#pragma unroll
        for (int ks = 0; ks < 4; ks++) {
            uint32_t ap[4] = {pp[2 * ks][0], pp[2 * ks][1], pp[2 * ks + 1][0], pp[2 * ks + 1][1]};
#pragma unroll
            for (int jn = 0; jn < 4; jn++) {
                uint32_t bb[2];
                int o = vbase + (jn * 8 + gid) * SKW + ks * 8 + tig;
                bb[0] = Vt[o];
                bb[1] = Vt[o + 4];
                mma_f16(O[jn], ap, bb);
            }
        }

        if (kb < qb) {   // stage next tile into other buffer
            int nb = ((kb + 1) & 1);
            *(uint4*)&Ks[nb * KTW + kv * SKW + hfk * 8]     = pk0;
            *(uint4*)&Ks[nb * KTW + kv * SKW + hfk * 8 + 4] = pk1;
            *(uint4*)&Vt[nb * VTW + dh * SKW + qv * 8]      = pv0;
            *(uint4*)&Vt[nb * VTW + dh * SKW + qv * 8 + 4]  = pv1;
        }
    }

    // write out (half)
    float inv_lo = 1.f / l_lo, inv_hi = 1.f / l_hi;
    __half* crow_lo = ctxh + ((size_t)row_lo * BATCH + b) * DMODEL + h * 32;
    __half* crow_hi = crow_lo + (size_t)8 * BATCH * DMODEL;
#pragma unroll
    for (int jn = 0; jn < 4; jn++) {
        int d = jn * 8 + 2 * tig;
        *(uint32_t*)(crow_lo + d) = packh2(O[jn][0] * inv_lo, O[jn][1] * inv_lo);
        *(uint32_t*)(crow_hi + d) = packh2(O[jn][2] * inv_hi, O[jn][3] * inv_hi);
    }
}

// ---------------- launch ----------------
struct LayerW {
    const float *ln1w, *ln1b, *wqkv, *bqkv, *wo, *bo, *ln2w, *ln2b, *wfc, *bfc, *wproj, *bproj;
};

extern "C" void kernel_launch(void* const* d_in, const int* in_sizes, int n_in,
                              void* d_out, int out_size) {
    const int*   ids  = (const int*)d_in[0];
    const int*   pos  = (const int*)d_in[1];
    const float* wte  = (const float*)d_in[3];
    const float* wpe  = (const float*)d_in[4];
    LayerW L[2];
    for (int l = 0; l < 2; l++) {
        int o = 5 + l * 12;
        L[l].ln1w  = (const float*)d_in[o + 0];
        L[l].ln1b  = (const float*)d_in[o + 1];
        L[l].wqkv  = (const float*)d_in[o + 2];
        L[l].bqkv  = (const float*)d_in[o + 3];
        L[l].wo    = (const float*)d_in[o + 4];
        L[l].bo    = (const float*)d_in[o + 5];
        L[l].ln2w  = (const float*)d_in[o + 6];
        L[l].ln2b  = (const float*)d_in[o + 7];
        L[l].wfc   = (const float*)d_in[o + 8];
        L[l].bfc   = (const float*)d_in[o + 9];
        L[l].wproj = (const float*)d_in[o + 10];
        L[l].bproj = (const float*)d_in[o + 11];
    }
    const float* lnfw = (const float*)d_in[29];
    const float* lnfb = (const float*)d_in[30];
    float* out = (float*)d_out;

    float*  x    = nullptr; cudaGetSymbolAddress((void**)&x,    g_x);
    __half* hh   = nullptr; cudaGetSymbolAddress((void**)&hh,   g_hh);
    __half* wh   = nullptr; cudaGetSymbolAddress((void**)&wh,   g_wh);
    __half* qh   = nullptr; cudaGetSymbolAddress((void**)&qh,   g_qh);
    __half* kh   = nullptr; cudaGetSymbolAddress((void**)&kh,   g_kh);
    __half* vt   = nullptr; cudaGetSymbolAddress((void**)&vt,   g_vt);
    __half* ctxh = nullptr; cudaGetSymbolAddress((void**)&ctxh, g_ctxh);
    __half* mh   = nullptr; cudaGetSymbolAddress((void**)&mh,   g_mh);

    embed_kernel<<<NTOK, 256>>>(ids, pos, wte, wpe, x);

    for (int l = 0; l < 2; l++) {
        // LN1 -> half
        ln_kernel<1><<<NTOK, 256>>>(x, L[l].ln1w, L[l].ln1b, nullptr, hh);
        // qkv = hh @ wqkv^T + bqkv -> scattered q/k/vt
        cvt_half_kernel<<<(QKVDIM * DMODEL) / 2048, 256>>>(L[l].wqkv, wh, QKVDIM * DMODEL);
        {
            dim3 g(QKVDIM / 128, NTOK / 128);
            gemm_h<0><<<g, 256>>>(hh, wh, L[l].bqkv, nullptr, nullptr, nullptr,
                                  qh, kh, vt, NTOK, QKVDIM, DMODEL);
        }
        // attention
        {
            dim3 g(SEQ / 64, BATCH * NHEAD);
            attn_mma<<<g, 128>>>(qh, kh, vt, ctxh);
        }
        // x = x + ctx @ wo^T + bo
        cvt_half_kernel<<<(DMODEL * DMODEL) / 2048, 256>>>(L[l].wo, wh, DMODEL * DMODEL);
        {
            dim3 g(DMODEL / 128, NTOK / 128);
            gemm_h<1><<<g, 256>>>(ctxh, wh, L[l].bo, x, x, nullptr,
                                  nullptr, nullptr, nullptr, NTOK, DMODEL, DMODEL);
        }
        // LN2 -> half
        ln_kernel<1><<<NTOK, 256>>>(x, L[l].ln2w, L[l].ln2b, nullptr, hh);
        // m = gelu(hh @ wfc^T + bfc) -> half
        cvt_half_kernel<<<(FFDIM * DMODEL) / 2048, 256>>>(L[l].wfc, wh, FFDIM * DMODEL);
        {
            dim3 g(FFDIM / 128, NTOK / 128);
            gemm_h<2><<<g, 256>>>(hh, wh, L[l].bfc, nullptr, nullptr, mh,
                                  nullptr, nullptr, nullptr, NTOK, FFDIM, DMODEL);
        }
        // x = x + m @ wproj^T + bproj
        cvt_half_kernel<<<(DMODEL * FFDIM) / 2048, 256>>>(L[l].wproj, wh, DMODEL * FFDIM);
        {
            dim3 g(DMODEL / 128, NTOK / 128);
            gemm_h<1><<<g, 256>>>(mh, wh, L[l].bproj, x, x, nullptr,
                                  nullptr, nullptr, nullptr, NTOK, DMODEL, FFDIM);
        }
    }

    // final LN -> fp32 out
    ln_kernel<0><<<NTOK, 256>>>(x, lnfw, lnfb, out, nullptr);
    (void)in_sizes; (void)n_in; (void)out_size;
}

// round 17
// speedup vs baseline: 11.5574x; 1.1170x over previous
#include <cuda_runtime.h>
#include <cuda_fp16.h>
#include <cstdint>
#include <math.h>

// Problem constants
#define SEQ 1536
#define BATCH 2
#define DMODEL 768
#define NHEAD 24
#define DHEAD 32
#define FFDIM 3072
#define NTOK (SEQ * BATCH)
#define QKVDIM (3 * DMODEL)
#define ATTN_SCALE 0.17677669529663688f
#define HSIZE (BATCH * NHEAD * SEQ * DHEAD)

// ---------------- scratch ----------------
__device__ float  g_x[NTOK * DMODEL];        // residual stream fp32
__device__ __half g_hh[NTOK * DMODEL];       // LN out (half)
__device__ __half g_wh[FFDIM * DMODEL];      // converted weight (half), reused
__device__ __half g_qh[HSIZE];               // Q pre-scaled  [b][h][s][dh]
__device__ __half g_kh[HSIZE];               // K             [b][h][s][dh]
__device__ __half g_vt[HSIZE];               // V transposed  [b][h][dh][s]
__device__ __half g_ctxh[NTOK * DMODEL];     // attention out (half)
__device__ __half g_mh[NTOK * FFDIM];        // gelu out (half)

__device__ __forceinline__ uint32_t packh2(float lo, float hi) {
    __half2 h = __floats2half2_rn(lo, hi);
    return *reinterpret_cast<uint32_t*>(&h);
}

__device__ __forceinline__ void mma_f16(float* d, const uint32_t* a, const uint32_t* b) {
    asm volatile(
        "mma.sync.aligned.m16n8k16.row.col.f32.f16.f16.f32 "
        "{%0,%1,%2,%3}, {%4,%5,%6,%7}, {%8,%9}, {%0,%1,%2,%3};"
        : "+f"(d[0]), "+f"(d[1]), "+f"(d[2]), "+f"(d[3])
        : "r"(a[0]), "r"(a[1]), "r"(a[2]), "r"(a[3]), "r"(b[0]), "r"(b[1]));
}

__device__ __forceinline__ uint32_t smem_u32(const void* p) {
    uint32_t a;
    asm("{ .reg .u64 t; cvta.to.shared.u64 t, %1; cvt.u32.u64 %0, t; }" : "=r"(a) : "l"(p));
    return a;
}
__device__ __forceinline__ void cp16(uint32_t dst, const void* src) {
    asm volatile("cp.async.cg.shared.global [%0], [%1], 16;" :: "r"(dst), "l"(src));
}
#define CP_COMMIT() asm volatile("cp.async.commit_group;" ::: "memory")
#define CP_WAIT(n)  asm volatile("cp.async.wait_group %0;" :: "n"(n) : "memory")

// ---------------- fp32 -> half convert (weights) ----------------
__global__ void cvt_half_kernel(const float* __restrict__ in, __half* __restrict__ out, int n) {
    int i = (blockIdx.x * 256 + threadIdx.x) * 8;
    if (i >= n) return;
    float4 a = *(const float4*)(in + i);
    float4 b = *(const float4*)(in + i + 4);
    uint4 u = make_uint4(packh2(a.x, a.y), packh2(a.z, a.w), packh2(b.x, b.y), packh2(b.z, b.w));
    *(uint4*)(out + i) = u;
}

// ---------------- embedding ----------------
__global__ void embed_kernel(const int* __restrict__ ids, const int* __restrict__ pos,
                             const float* __restrict__ wte, const float* __restrict__ wpe,
                             float* __restrict__ x) {
    int t = blockIdx.x;
    int s = t / BATCH, b = t % BATCH;
    int id = ids[b * SEQ + s];
    int p  = pos[b * SEQ + s];
    const float* te = wte + (size_t)id * DMODEL;
    const float* pe = wpe + (size_t)p * DMODEL;
    for (int d = threadIdx.x; d < DMODEL; d += blockDim.x)
        x[(size_t)t * DMODEL + d] = te[d] + pe[d];
}

// ---------------- layernorm (OUT_HALF: write half buffer, else fp32) ----------------
template <int OUT_HALF>
__global__ void ln_kernel(const float* __restrict__ in, const float* __restrict__ w,
                          const float* __restrict__ b, float* __restrict__ outf,
                          __half* __restrict__ outh) {
    int t = blockIdx.x;
    const float* row = in + (size_t)t * DMODEL;
    float s = 0.f, ss = 0.f;
    for (int d = threadIdx.x; d < DMODEL; d += 256) {
        float v = row[d];
        s += v;
        ss = fmaf(v, v, ss);
    }
    __shared__ float red0[8], red1[8];
    __shared__ float s_mu, s_inv;
    int lane = threadIdx.x & 31, wid = threadIdx.x >> 5;
#pragma unroll
    for (int o = 16; o; o >>= 1) {
        s  += __shfl_xor_sync(0xffffffffu, s, o);
        ss += __shfl_xor_sync(0xffffffffu, ss, o);
    }
    if (lane == 0) { red0[wid] = s; red1[wid] = ss; }
    __syncthreads();
    if (threadIdx.x == 0) {
        float a = 0.f, c = 0.f;
#pragma unroll
        for (int i = 0; i < 8; i++) { a += red0[i]; c += red1[i]; }
        float mu = a * (1.0f / DMODEL);
        float var = c * (1.0f / DMODEL) - mu * mu;
        s_mu = mu;
        s_inv = rsqrtf(var + 1e-5f);
    }
    __syncthreads();
    float mu = s_mu, inv = s_inv;
    for (int d = threadIdx.x; d < DMODEL; d += 256) {
        float v = (row[d] - mu) * inv * w[d] + b[d];
        if (OUT_HALF) outh[(size_t)t * DMODEL + d] = __float2half(v);
        else          outf[(size_t)t * DMODEL + d] = v;
    }
}

// ---------------- half-input tensor-core GEMM, 3-stage cp.async pipeline ----------------
// C = A @ W^T + bias (+epilogue). A:(M,K) half, W:(N,K) half, row-major.
// BM=BN=128, BK=32, 8 warps (4Mx2N), warp tile 32x64 = 2x8 m16n8k16, fp32 accum.
// SMEM word layout off(k2,m) = (k2>>2)*512 + m*4 + (k2&3); stage stride 2048 words.
// Pipeline (per iter): wait_group(1) -> barrier -> issue copy chunk c+2 -> compute chunk c.
// The copy issued at iter c overwrites the stage computed at iter c-1; the barrier
// at iter c guarantees all threads finished that compute. One barrier per iteration.
// EPI: 0 = qkv-scatter (q scaled, k rows, v transposed)
//      1 = bias + residual -> fp32
//      2 = bias + exact GELU -> half
#define NSTAGE 3
template <int EPI>
__global__ void __launch_bounds__(256) gemm_h(const __half* __restrict__ A,
                                              const __half* __restrict__ W,
                                              const float* __restrict__ bias,
                                              const float* __restrict__ res,
                                              float* __restrict__ Cf,
                                              __half* __restrict__ Ch,
                                              __half* __restrict__ qh,
                                              __half* __restrict__ kh,
                                              __half* __restrict__ vt,
                                              int M, int N, int K) {
    __shared__ uint32_t Sa[NSTAGE * 2048];   // 24 KB
    __shared__ uint32_t Sw[NSTAGE * 2048];   // 24 KB

    int tid = threadIdx.x;
    int m0 = blockIdx.y * 128, n0 = blockIdx.x * 128;
    int warp = tid >> 5, lane = tid & 31;
    int wm = warp & 3, wn = warp >> 2;
    int gid = lane >> 2, tig = lane & 3;

    float acc[2][8][4];
#pragma unroll
    for (int i = 0; i < 2; i++)
#pragma unroll
        for (int j = 0; j < 8; j++)
#pragma unroll
            for (int r = 0; r < 4; r++) acc[i][j][r] = 0.f;

    // copy roles: r = row (0..127), hf = which 16-half group of the 32-half chunk
    int r = tid & 127, hf = tid >> 7;
    const __half* Ap = A + (size_t)(m0 + r) * K + hf * 16;
    const __half* Wp = W + (size_t)(n0 + r) * K + hf * 16;
    int sb0 = (2 * hf) * 512 + r * 4;        // word offset, k2 group 2hf
    // byte addresses in shared
    uint32_t a0 = smem_u32(Sa) + (uint32_t)sb0 * 4;
    uint32_t a1 = a0 + 512 * 4;              // k2 group 2hf+1 lives +512 words
    uint32_t w0 = smem_u32(Sw) + (uint32_t)sb0 * 4;
    uint32_t w1 = w0 + 512 * 4;

    int nch = K >> 5;
    // prologue: stage chunks 0..NSTAGE-2
#pragma unroll
    for (int s = 0; s < NSTAGE - 1; s++) {
        uint32_t off = (uint32_t)s * 8192;   // 2048 words * 4B
        cp16(a0 + off, Ap + (size_t)s * 32);
        cp16(a1 + off, Ap + (size_t)s * 32 + 8);
        cp16(w0 + off, Wp + (size_t)s * 32);
        cp16(w1 + off, Wp + (size_t)s * 32 + 8);
        CP_COMMIT();
    }

    int st = 0;
    for (int c = 0; c < nch; c++) {
        CP_WAIT(1);                          // chunk c complete (newest may pend)
        __syncthreads();                     // publish + retire compute of iter c-1
        int pc = c + NSTAGE - 1;
        if (pc < nch) {
            int ps = pc % NSTAGE;
            uint32_t off = (uint32_t)ps * 8192;
            cp16(a0 + off, Ap + (size_t)pc * 32);
            cp16(a1 + off, Ap + (size_t)pc * 32 + 8);
            cp16(w0 + off, Wp + (size_t)pc * 32);
            cp16(w1 + off, Wp + (size_t)pc * 32 + 8);
        }
        CP_COMMIT();                         // commit (possibly empty) to keep counts aligned

        int bo = st * 2048;
#pragma unroll
        for (int s = 0; s < 2; s++) {
            int base = bo + s * 1024;
            uint32_t a[2][4], b[8][2];
#pragma unroll
            for (int i = 0; i < 2; i++) {
                int o = base + (wm * 32 + i * 16 + gid) * 4 + tig;
                a[i][0] = Sa[o];
                a[i][1] = Sa[o + 32];
                a[i][2] = Sa[o + 512];
                a[i][3] = Sa[o + 544];
            }
#pragma unroll
            for (int j = 0; j < 8; j++) {
                int o = base + (wn * 64 + j * 8 + gid) * 4 + tig;
                b[j][0] = Sw[o];
                b[j][1] = Sw[o + 512];
            }
#pragma unroll
            for (int i = 0; i < 2; i++)
#pragma unroll
                for (int j = 0; j < 8; j++)
                    mma_f16(acc[i][j], a[i], b[j]);
        }
        st = (st + 1 == NSTAGE) ? 0 : st + 1;
    }

    // epilogue
#pragma unroll
    for (int i = 0; i < 2; i++) {
        int mrow = m0 + wm * 32 + i * 16 + gid;
#pragma unroll
        for (int j = 0; j < 8; j++) {
            int n = n0 + wn * 64 + j * 8 + tig * 2;
            float bn0 = bias[n], bn1 = bias[n + 1];
#pragma unroll
            for (int hh = 0; hh < 2; hh++) {
                int m = mrow + hh * 8;
                float v0 = acc[i][j][hh * 2 + 0] + bn0;
                float v1 = acc[i][j][hh * 2 + 1] + bn1;
                if (EPI == 0) {
                    // qkv scatter: m = s*BATCH+b ; n -> head, component
                    int s = m >> 1, bb = m & 1;
                    int hd = n / 96, c = n % 96;
                    size_t hb = (size_t)(bb * NHEAD + hd);
                    if (c < 32) {
                        *(uint32_t*)(qh + (hb * SEQ + s) * 32 + c) =
                            packh2(v0 * ATTN_SCALE, v1 * ATTN_SCALE);
                    } else if (c < 64) {
                        *(uint32_t*)(kh + (hb * SEQ + s) * 32 + (c - 32)) = packh2(v0, v1);
                    } else {
                        vt[(hb * 32 + (c - 64)) * SEQ + s] = __float2half(v0);
                        vt[(hb * 32 + (c - 63)) * SEQ + s] = __float2half(v1);
                    }
                } else if (EPI == 1) {
                    v0 += res[(size_t)m * N + n];
                    v1 += res[(size_t)m * N + n + 1];
                    *(float2*)&Cf[(size_t)m * N + n] = make_float2(v0, v1);
                } else {
                    v0 = 0.5f * v0 * (1.0f + erff(v0 * 0.70710678118654752f));
                    v1 = 0.5f * v1 * (1.0f + erff(v1 * 0.70710678118654752f));
                    *(uint32_t*)(Ch + (size_t)m * N + n) = packh2(v0, v1);
                }
            }
        }
    }
}

// ---------------- flash attention, half inputs, double-buffered tiles ----------------
#define SKW 36
#define KTW (64 * SKW)    // K tile words
#define VTW (32 * SKW)    // V tile words
__global__ void __launch_bounds__(128) attn_mma(const __half* __restrict__ qh,
                                                const __half* __restrict__ kh,
                                                const __half* __restrict__ vt,
                                                __half* __restrict__ ctxh) {
    __shared__ uint32_t Ks[2 * KTW];
    __shared__ uint32_t Vt[2 * VTW];

    int tid = threadIdx.x;
    int warp = tid >> 5, lane = tid & 31;
    int gid = lane >> 2, tig = lane & 3;
    int qb = gridDim.x - 1 - blockIdx.x;       // big blocks first
    int q0 = qb * 64;
    int bh = blockIdx.y;
    int b = bh / NHEAD, h = bh % NHEAD;
    size_t hb = (size_t)(b * NHEAD + h);

    const __half* khh = kh + hb * SEQ * 32;
    const __half* vth = vt + hb * 32 * SEQ;

    int row_lo = q0 + warp * 16 + gid;

    // Q fragments (pre-scaled in qkv epilogue): direct uint32 loads
    uint32_t aq[2][4];
    {
        const __half* qlo = qh + (hb * SEQ + row_lo) * 32;
        const __half* qhi = qlo + 8 * 32;
#pragma unroll
        for (int ks = 0; ks < 2; ks++) {
            int d0 = ks * 16 + 2 * tig;
            aq[ks][0] = *(const uint32_t*)(qlo + d0);
            aq[ks][1] = *(const uint32_t*)(qhi + d0);
            aq[ks][2] = *(const uint32_t*)(qlo + d0 + 8);
            aq[ks][3] = *(const uint32_t*)(qhi + d0 + 8);
        }
    }

    float m_lo = -1e30f, m_hi = -1e30f, l_lo = 0.f, l_hi = 0.f;
    float O[4][4];
#pragma unroll
    for (int j = 0; j < 4; j++)
#pragma unroll
        for (int r = 0; r < 4; r++) O[j][r] = 0.f;

    // copy roles
    int kv = tid >> 1, hfk = tid & 1;          // K: row, 16-half group
    int dh = tid >> 2, qv = tid & 3;           // V: dh row, 16-half group along kv

    // prologue: tile 0 -> buffer 0
    {
        const __half* kr = khh + (size_t)kv * 32 + hfk * 16;
        uint4 k0 = *(const uint4*)kr;
        uint4 k1 = *(const uint4*)(kr + 8);
        *(uint4*)&Ks[kv * SKW + hfk * 8]     = k0;
        *(uint4*)&Ks[kv * SKW + hfk * 8 + 4] = k1;
        const __half* vr = vth + (size_t)dh * SEQ + qv * 16;
        uint4 v0 = *(const uint4*)vr;
        uint4 v1 = *(const uint4*)(vr + 8);
        *(uint4*)&Vt[dh * SKW + qv * 8]     = v0;
        *(uint4*)&Vt[dh * SKW + qv * 8 + 4] = v1;
    }

    for (int kb = 0; kb <= qb; kb++) {
        __syncthreads();                       // buffer kb&1 ready
        uint4 pk0, pk1, pv0, pv1;
        if (kb < qb) {
            const __half* kr = khh + (size_t)((kb + 1) * 64 + kv) * 32 + hfk * 16;
            pk0 = *(const uint4*)kr;
            pk1 = *(const uint4*)(kr + 8);
            const __half* vr = vth + (size_t)dh * SEQ + (kb + 1) * 64 + qv * 16;
            pv0 = *(const uint4*)vr;
            pv1 = *(const uint4*)(vr + 8);
        }
        int kbase = (kb & 1) * KTW, vbase = (kb & 1) * VTW;

        // scores
        float sc[8][4];
#pragma unroll
        for (int j = 0; j < 8; j++) {
            sc[j][0] = sc[j][1] = sc[j][2] = sc[j][3] = 0.f;
#pragma unroll
            for (int ks = 0; ks < 2; ks++) {
                uint32_t bb[2];
                int o = kbase + (j * 8 + gid) * SKW + ks * 8 + tig;
                bb[0] = Ks[o];
                bb[1] = Ks[o + 4];
                mma_f16(sc[j], aq[ks], bb);
            }
        }

        if (kb == qb) {   // causal mask on diagonal tile
            int rl = warp * 16 + gid, rh = rl + 8;
#pragma unroll
            for (int j = 0; j < 8; j++) {
                int c0 = j * 8 + 2 * tig, c1 = c0 + 1;
                if (c0 > rl) sc[j][0] = -1e30f;
                if (c1 > rl) sc[j][1] = -1e30f;
                if (c0 > rh) sc[j][2] = -1e30f;
                if (c1 > rh) sc[j][3] = -1e30f;
            }
        }

        // online softmax
        float mt_lo = -1e30f, mt_hi = -1e30f;
#pragma unroll
        for (int j = 0; j < 8; j++) {
            mt_lo = fmaxf(mt_lo, fmaxf(sc[j][0], sc[j][1]));
            mt_hi = fmaxf(mt_hi, fmaxf(sc[j][2], sc[j][3]));
        }
        mt_lo = fmaxf(mt_lo, __shfl_xor_sync(0xffffffffu, mt_lo, 1));
        mt_lo = fmaxf(mt_lo, __shfl_xor_sync(0xffffffffu, mt_lo, 2));
        mt_hi = fmaxf(mt_hi, __shfl_xor_sync(0xffffffffu, mt_hi, 1));
        mt_hi = fmaxf(mt_hi, __shfl_xor_sync(0xffffffffu, mt_hi, 2));

        float mn_lo = fmaxf(m_lo, mt_lo), mn_hi = fmaxf(m_hi, mt_hi);
        float corr_lo = __expf(m_lo - mn_lo), corr_hi = __expf(m_hi - mn_hi);
        m_lo = mn_lo;
        m_hi = mn_hi;

        uint32_t pp[8][2];
        float rs_lo = 0.f, rs_hi = 0.f;
#pragma unroll
        for (int j = 0; j < 8; j++) {
            float p0 = __expf(sc[j][0] - mn_lo);
            float p1 = __expf(sc[j][1] - mn_lo);
            float p2 = __expf(sc[j][2] - mn_hi);
            float p3 = __expf(sc[j][3] - mn_hi);
            rs_lo += p0 + p1;
            rs_hi += p2 + p3;
            pp[j][0] = packh2(p0, p1);
            pp[j][1] = packh2(p2, p3);
        }
        rs_lo += __shfl_xor_sync(0xffffffffu, rs_lo, 1);
        rs_lo += __shfl_xor_sync(0xffffffffu, rs_lo, 2);
        rs_hi += __shfl_xor_sync(0xffffffffu, rs_hi, 1);
        rs_hi += __shfl_xor_sync(0xffffffffu, rs_hi, 2);
        l_lo = l_lo * corr_lo + rs_lo;
        l_hi = l_hi * corr_hi + rs_hi;

#pragma unroll
        for (int j = 0; j < 4; j++) {
            O[j][0] *= corr_lo; O[j][1] *= corr_lo;
            O[j][2] *= corr_hi; O[j][3] *= corr_hi;
        }

        // P·V
#pragma unroll
        for (int ks = 0; ks < 4; ks++) {
            uint32_t ap[4] = {pp[2 * ks][0], pp[2 * ks][1], pp[2 * ks + 1][0], pp[2 * ks + 1][1]};
#pragma unroll
            for (int jn = 0; jn < 4; jn++) {
                uint32_t bb[2];
                int o = vbase + (jn * 8 + gid) * SKW + ks * 8 + tig;
                bb[0] = Vt[o];
                bb[1] = Vt[o + 4];
                mma_f16(O[jn], ap, bb);
            }
        }

        if (kb < qb) {   // stage next tile into other buffer
            int nb = ((kb + 1) & 1);
            *(uint4*)&Ks[nb * KTW + kv * SKW + hfk * 8]     = pk0;
            *(uint4*)&Ks[nb * KTW + kv * SKW + hfk * 8 + 4] = pk1;
            *(uint4*)&Vt[nb * VTW + dh * SKW + qv * 8]      = pv0;
            *(uint4*)&Vt[nb * VTW + dh * SKW + qv * 8 + 4]  = pv1;
        }
    }

    // write out (half)
    float inv_lo = 1.f / l_lo, inv_hi = 1.f / l_hi;
    __half* crow_lo = ctxh + ((size_t)row_lo * BATCH + b) * DMODEL + h * 32;
    __half* crow_hi = crow_lo + (size_t)8 * BATCH * DMODEL;
#pragma unroll
    for (int jn = 0; jn < 4; jn++) {
        int d = jn * 8 + 2 * tig;
        *(uint32_t*)(crow_lo + d) = packh2(O[jn][0] * inv_lo, O[jn][1] * inv_lo);
        *(uint32_t*)(crow_hi + d) = packh2(O[jn][2] * inv_hi, O[jn][3] * inv_hi);
    }
}

// ---------------- launch ----------------
struct LayerW {
    const float *ln1w, *ln1b, *wqkv, *bqkv, *wo, *bo, *ln2w, *ln2b, *wfc, *bfc, *wproj, *bproj;
};

extern "C" void kernel_launch(void* const* d_in, const int* in_sizes, int n_in,
                              void* d_out, int out_size) {
    const int*   ids  = (const int*)d_in[0];
    const int*   pos  = (const int*)d_in[1];
    const float* wte  = (const float*)d_in[3];
    const float* wpe  = (const float*)d_in[4];
    LayerW L[2];
    for (int l = 0; l < 2; l++) {
        int o = 5 + l * 12;
        L[l].ln1w  = (const float*)d_in[o + 0];
        L[l].ln1b  = (const float*)d_in[o + 1];
        L[l].wqkv  = (const float*)d_in[o + 2];
        L[l].bqkv  = (const float*)d_in[o + 3];
        L[l].wo    = (const float*)d_in[o + 4];
        L[l].bo    = (const float*)d_in[o + 5];
        L[l].ln2w  = (const float*)d_in[o + 6];
        L[l].ln2b  = (const float*)d_in[o + 7];
        L[l].wfc   = (const float*)d_in[o + 8];
        L[l].bfc   = (const float*)d_in[o + 9];
        L[l].wproj = (const float*)d_in[o + 10];
        L[l].bproj = (const float*)d_in[o + 11];
    }
    const float* lnfw = (const float*)d_in[29];
    const float* lnfb = (const float*)d_in[30];
    float* out = (float*)d_out;

    float*  x    = nullptr; cudaGetSymbolAddress((void**)&x,    g_x);
    __half* hh   = nullptr; cudaGetSymbolAddress((void**)&hh,   g_hh);
    __half* wh   = nullptr; cudaGetSymbolAddress((void**)&wh,   g_wh);
    __half* qh   = nullptr; cudaGetSymbolAddress((void**)&qh,   g_qh);
    __half* kh   = nullptr; cudaGetSymbolAddress((void**)&kh,   g_kh);
    __half* vt   = nullptr; cudaGetSymbolAddress((void**)&vt,   g_vt);
    __half* ctxh = nullptr; cudaGetSymbolAddress((void**)&ctxh, g_ctxh);
    __half* mh   = nullptr; cudaGetSymbolAddress((void**)&mh,   g_mh);

    embed_kernel<<<NTOK, 256>>>(ids, pos, wte, wpe, x);

    for (int l = 0; l < 2; l++) {
        // LN1 -> half
        ln_kernel<1><<<NTOK, 256>>>(x, L[l].ln1w, L[l].ln1b, nullptr, hh);
        // qkv = hh @ wqkv^T + bqkv -> scattered q/k/vt
        cvt_half_kernel<<<(QKVDIM * DMODEL) / 2048, 256>>>(L[l].wqkv, wh, QKVDIM * DMODEL);
        {
            dim3 g(QKVDIM / 128, NTOK / 128);
            gemm_h<0><<<g, 256>>>(hh, wh, L[l].bqkv, nullptr, nullptr, nullptr,
                                  qh, kh, vt, NTOK, QKVDIM, DMODEL);
        }
        // attention
        {
            dim3 g(SEQ / 64, BATCH * NHEAD);
            attn_mma<<<g, 128>>>(qh, kh, vt, ctxh);
        }
        // x = x + ctx @ wo^T + bo
        cvt_half_kernel<<<(DMODEL * DMODEL) / 2048, 256>>>(L[l].wo, wh, DMODEL * DMODEL);
        {
            dim3 g(DMODEL / 128, NTOK / 128);
            gemm_h<1><<<g, 256>>>(ctxh, wh, L[l].bo, x, x, nullptr,
                                  nullptr, nullptr, nullptr, NTOK, DMODEL, DMODEL);
        }
        // LN2 -> half
        ln_kernel<1><<<NTOK, 256>>>(x, L[l].ln2w, L[l].ln2b, nullptr, hh);
        // m = gelu(hh @ wfc^T + bfc) -> half
        cvt_half_kernel<<<(FFDIM * DMODEL) / 2048, 256>>>(L[l].wfc, wh, FFDIM * DMODEL);
        {
            dim3 g(FFDIM / 128, NTOK / 128);
            gemm_h<2><<<g, 256>>>(hh, wh, L[l].bfc, nullptr, nullptr, mh,
                                  nullptr, nullptr, nullptr, NTOK, FFDIM, DMODEL);
        }
        // x = x + m @ wproj^T + bproj
        cvt_half_kernel<<<(DMODEL * FFDIM) / 2048, 256>>>(L[l].wproj, wh, DMODEL * FFDIM);
        {
            dim3 g(DMODEL / 128, NTOK / 128);
            gemm_h<1><<<g, 256>>>(mh, wh, L[l].bproj, x, x, nullptr,
                                  nullptr, nullptr, nullptr, NTOK, DMODEL, FFDIM);
        }
    }

    // final LN -> fp32 out
    ln_kernel<0><<<NTOK, 256>>>(x, lnfw, lnfb, out, nullptr);
    (void)in_sizes; (void)n_in; (void)out_size;
}